// round 1
// baseline (speedup 1.0000x reference)
#include <cuda_runtime.h>
#include <math.h>

#define Nn 50000
#define Ee 800000
#define Dd 128

// ---------------- scratch (static device globals; no allocation) ----------------
__device__ float g_q[Nn * Dd];
__device__ float g_k[Nn * Dd];
__device__ float g_v[Nn * Dd];
__device__ float g_e[(size_t)Ee * Dd];   // 409.6 MB edge features
__device__ float g_alpha[Ee * 2];        // alpha, then overwritten with exp()
__device__ float g_amax[Nn * 2];
__device__ float g_denom[Nn * 2];

__device__ __forceinline__ void atomicMaxF(float* addr, float v) {
    if (v >= 0.0f) atomicMax((int*)addr, __float_as_int(v));
    else           atomicMin((unsigned int*)addr, __float_as_uint(v));
}

// ---------------- init segment-softmax accumulators ----------------
__global__ void k_init() {
    int i = blockIdx.x * blockDim.x + threadIdx.x;
    if (i < Nn * 2) {
        g_amax[i]  = -INFINITY;
        g_denom[i] = 0.0f;
    }
}

// ---------------- K1: node GEMMs q/k/v/skip ----------------
// blockIdx.y selects the matrix. Tile: 64 nodes x 128 cols, BK=32.
// 256 threads, each computes 8 nodes x 4 cols.
__global__ void __launch_bounds__(256) k_node_gemm(
    const float* __restrict__ x,
    const float* __restrict__ Wq, const float* __restrict__ bq,
    const float* __restrict__ Wk, const float* __restrict__ bk,
    const float* __restrict__ Wv, const float* __restrict__ bv,
    const float* __restrict__ Ws, const float* __restrict__ bs,
    float* __restrict__ out)
{
    __shared__ float s_x[64][32];
    __shared__ float s_w[32][128];

    int mat = blockIdx.y;
    const float* W = (mat == 0) ? Wq : (mat == 1) ? Wk : (mat == 2) ? Wv : Ws;
    const float* b = (mat == 0) ? bq : (mat == 1) ? bk : (mat == 2) ? bv : bs;
    float* dst     = (mat == 0) ? g_q : (mat == 1) ? g_k : (mat == 2) ? g_v : out;

    int tid = threadIdx.x;
    int n0  = blockIdx.x * 64;
    int cc  = tid & 31;          // column group: cols cc*4 .. cc*4+3
    int ng  = (tid >> 5) * 8;    // base local node

    float acc[8][4];
#pragma unroll
    for (int i = 0; i < 8; i++)
#pragma unroll
        for (int j = 0; j < 4; j++) acc[i][j] = 0.0f;

    for (int kc = 0; kc < 128; kc += 32) {
        // fill W chunk: 32x128 floats = 1024 float4
#pragma unroll
        for (int i = 0; i < 4; i++) {
            int idx = tid + i * 256;
            int r = idx >> 5, c4 = idx & 31;
            *(float4*)&s_w[r][c4 * 4] = *(const float4*)&W[(kc + r) * 128 + c4 * 4];
        }
        // fill x chunk: 64x32 floats = 512 float4
#pragma unroll
        for (int i = 0; i < 2; i++) {
            int idx = tid + i * 256;
            int nl = idx >> 3, k4 = idx & 7;
            int n = n0 + nl;
            float4 v = (n < Nn) ? *(const float4*)&x[(size_t)n * 128 + kc + k4 * 4]
                                : make_float4(0.f, 0.f, 0.f, 0.f);
            *(float4*)&s_x[nl][k4 * 4] = v;
        }
        __syncthreads();

#pragma unroll
        for (int kk = 0; kk < 32; kk += 4) {
            float4 w0 = *(float4*)&s_w[kk + 0][cc * 4];
            float4 w1 = *(float4*)&s_w[kk + 1][cc * 4];
            float4 w2 = *(float4*)&s_w[kk + 2][cc * 4];
            float4 w3 = *(float4*)&s_w[kk + 3][cc * 4];
#pragma unroll
            for (int n = 0; n < 8; n++) {
                float4 a = *(float4*)&s_x[ng + n][kk];
                acc[n][0] += a.x * w0.x + a.y * w1.x + a.z * w2.x + a.w * w3.x;
                acc[n][1] += a.x * w0.y + a.y * w1.y + a.z * w2.y + a.w * w3.y;
                acc[n][2] += a.x * w0.z + a.y * w1.z + a.z * w2.z + a.w * w3.z;
                acc[n][3] += a.x * w0.w + a.y * w1.w + a.z * w2.w + a.w * w3.w;
            }
        }
        __syncthreads();
    }

    float4 bias = *(const float4*)&b[cc * 4];
#pragma unroll
    for (int n = 0; n < 8; n++) {
        int row = n0 + ng + n;
        if (row < Nn) {
            float4 r = make_float4(acc[n][0] + bias.x, acc[n][1] + bias.y,
                                   acc[n][2] + bias.z, acc[n][3] + bias.w);
            *(float4*)&dst[(size_t)row * 128 + cc * 4] = r;
        }
    }
}

// ---------------- K2: edge pass A ----------------
// Per 64-edge tile: build edge_attr = [cos(rel_t*Wt+bt) | msg] chunk in smem,
// GEMM vs We, store e, compute alpha = q[dst].(k[src]+e)/8, atomicMax amax.
__global__ void __launch_bounds__(256) k_edge_a(
    const int*   __restrict__ ei,
    const float* __restrict__ last_update,
    const float* __restrict__ t,
    const float* __restrict__ msg,
    const float* __restrict__ Wt,
    const float* __restrict__ bt,
    const float* __restrict__ We)
{
    __shared__ float s_attr[64][32];
    __shared__ float s_we[32][128];
    __shared__ int   s_src[64], s_dst[64];
    __shared__ float s_relt[64];

    int tid = threadIdx.x;
    int e0  = blockIdx.x * 64;

    if (tid < 64) {
        int e = e0 + tid;
        int s = ei[e];
        s_src[tid]  = s;
        s_dst[tid]  = ei[Ee + e];
        s_relt[tid] = last_update[s] - t[e];
    }
    __syncthreads();

    float acc[8][4];
#pragma unroll
    for (int i = 0; i < 8; i++)
#pragma unroll
        for (int j = 0; j < 4; j++) acc[i][j] = 0.0f;

    int cc = tid & 31;
    int eg = (tid >> 5) * 8;

    for (int kc = 0; kc < 256; kc += 32) {
        // fill We chunk
#pragma unroll
        for (int i = 0; i < 4; i++) {
            int idx = tid + i * 256;
            int r = idx >> 5, c4 = idx & 31;
            *(float4*)&s_we[r][c4 * 4] = *(const float4*)&We[(kc + r) * 128 + c4 * 4];
        }
        // fill attr chunk (cos-time-enc for k<128, msg for k>=128)
#pragma unroll
        for (int i = 0; i < 8; i++) {
            int idx = tid + i * 256;           // 0..2047
            int el = idx >> 5, kl = idx & 31;
            int kg = kc + kl;
            float v;
            if (kg < 128) v = cosf(s_relt[el] * Wt[kg] + bt[kg]);
            else          v = msg[(size_t)(e0 + el) * 128 + (kg - 128)];
            s_attr[el][kl] = v;
        }
        __syncthreads();

#pragma unroll
        for (int kk = 0; kk < 32; kk += 4) {
            float4 w0 = *(float4*)&s_we[kk + 0][cc * 4];
            float4 w1 = *(float4*)&s_we[kk + 1][cc * 4];
            float4 w2 = *(float4*)&s_we[kk + 2][cc * 4];
            float4 w3 = *(float4*)&s_we[kk + 3][cc * 4];
#pragma unroll
            for (int e = 0; e < 8; e++) {
                float4 a = *(float4*)&s_attr[eg + e][kk];
                acc[e][0] += a.x * w0.x + a.y * w1.x + a.z * w2.x + a.w * w3.x;
                acc[e][1] += a.x * w0.y + a.y * w1.y + a.z * w2.y + a.w * w3.y;
                acc[e][2] += a.x * w0.z + a.y * w1.z + a.z * w2.z + a.w * w3.z;
                acc[e][3] += a.x * w0.w + a.y * w1.w + a.z * w2.w + a.w * w3.w;
            }
        }
        __syncthreads();
    }

    int head = cc >> 4;     // cols [0,64) = head 0, [64,128) = head 1
#pragma unroll
    for (int e = 0; e < 8; e++) {
        int el = eg + e;
        int ge = e0 + el;
        // store e for the aggregation pass
        float4 r = make_float4(acc[e][0], acc[e][1], acc[e][2], acc[e][3]);
        *(float4*)&g_e[(size_t)ge * 128 + cc * 4] = r;

        int s = s_src[el], d = s_dst[el];
        float4 qv = *(const float4*)&g_q[(size_t)d * 128 + cc * 4];
        float4 kv = *(const float4*)&g_k[(size_t)s * 128 + cc * 4];
        float p = qv.x * (kv.x + acc[e][0]) + qv.y * (kv.y + acc[e][1])
                + qv.z * (kv.z + acc[e][2]) + qv.w * (kv.w + acc[e][3]);
        // reduce within each 16-lane half (one head per half-warp)
        p += __shfl_xor_sync(0xffffffffu, p, 1);
        p += __shfl_xor_sync(0xffffffffu, p, 2);
        p += __shfl_xor_sync(0xffffffffu, p, 4);
        p += __shfl_xor_sync(0xffffffffu, p, 8);
        if ((cc & 15) == 0) {
            float alpha = p * 0.125f;   // / sqrt(64)
            g_alpha[ge * 2 + head] = alpha;
            atomicMaxF(&g_amax[d * 2 + head], alpha);
        }
    }
}

// ---------------- K3: exp + denominator ----------------
__global__ void k_expsum(const int* __restrict__ ei) {
    int i = blockIdx.x * blockDim.x + threadIdx.x;   // over E*2
    if (i >= Ee * 2) return;
    int e = i >> 1, h = i & 1;
    int d = ei[Ee + e];
    float ex = expf(g_alpha[i] - g_amax[d * 2 + h]);
    g_alpha[i] = ex;
    atomicAdd(&g_denom[d * 2 + h], ex);
}

// ---------------- K4: weighted aggregation (warp per edge) ----------------
__global__ void __launch_bounds__(256) k_agg(const int* __restrict__ ei,
                                             float* __restrict__ out)
{
    int gtid = blockIdx.x * blockDim.x + threadIdx.x;
    int e = gtid >> 5;
    if (e >= Ee) return;
    int lane = threadIdx.x & 31;

    int s = ei[e], d = ei[Ee + e];
    float2 ex  = *(const float2*)&g_alpha[e * 2];
    float2 den = *(const float2*)&g_denom[d * 2];
    float w = (lane < 16) ? (ex.x / den.x) : (ex.y / den.y);

    int c = lane * 4;
    float4 vv = *(const float4*)&g_v[(size_t)s * 128 + c];
    float4 ev = *(const float4*)&g_e[(size_t)e * 128 + c];
    float4 r;
    r.x = w * (vv.x + ev.x);
    r.y = w * (vv.y + ev.y);
    r.z = w * (vv.z + ev.z);
    r.w = w * (vv.w + ev.w);

    float* p = &out[(size_t)d * 128 + c];
    asm volatile("red.global.add.v4.f32 [%0], {%1, %2, %3, %4};"
                 :: "l"(p), "f"(r.x), "f"(r.y), "f"(r.z), "f"(r.w)
                 : "memory");
}

// ---------------- launch ----------------
extern "C" void kernel_launch(void* const* d_in, const int* in_sizes, int n_in,
                              void* d_out, int out_size)
{
    const float* x           = (const float*)d_in[0];
    const float* last_update = (const float*)d_in[1];
    const int*   ei          = (const int*)  d_in[2];
    const float* t           = (const float*)d_in[3];
    const float* msg         = (const float*)d_in[4];
    const float* Wt          = (const float*)d_in[5];
    const float* bt          = (const float*)d_in[6];
    const float* Wq          = (const float*)d_in[7];
    const float* bq          = (const float*)d_in[8];
    const float* Wk          = (const float*)d_in[9];
    const float* bk          = (const float*)d_in[10];
    const float* Wv          = (const float*)d_in[11];
    const float* bv          = (const float*)d_in[12];
    const float* We          = (const float*)d_in[13];
    const float* Wskip       = (const float*)d_in[14];
    const float* bskip       = (const float*)d_in[15];
    float* out = (float*)d_out;

    k_init<<<(Nn * 2 + 255) / 256, 256>>>();

    dim3 g1((Nn + 63) / 64, 4);
    k_node_gemm<<<g1, 256>>>(x, Wq, bq, Wk, bk, Wv, bv, Wskip, bskip, out);

    k_edge_a<<<Ee / 64, 256>>>(ei, last_update, t, msg, Wt, bt, We);

    k_expsum<<<(Ee * 2 + 255) / 256, 256>>>(ei);

    k_agg<<<(Ee * 32 + 255) / 256, 256>>>(ei, out);
}

// round 4
// speedup vs baseline: 1.8496x; 1.8496x over previous
#include <cuda_runtime.h>
#include <cuda_fp16.h>
#include <cstdint>
#include <math.h>

#define Nn 50000
#define Ee 800000
#define Dd 128

// ---------------- scratch (static device globals; no allocation) ----------------
__device__ __half g_xh[(size_t)Nn * Dd];
__device__ __half g_qh[(size_t)Nn * Dd];
__device__ __half g_kh[(size_t)Nn * Dd];
__device__ __half g_vh[(size_t)Nn * Dd];
__device__ __half g_Weh[128 * 256];        // [n][k] fp16 (transposed We)
__device__ __half g_Wallh[512 * 128];      // [j][k], j = {q|k|v|skip}*128+n
__device__ __half g_vj[(size_t)Ee * Dd];   // v[src]+e, fp16 (205MB)
__device__ float  g_alpha[Ee * 2];
__device__ float  g_amax[Nn * 2];
__device__ float  g_denom[Nn * 2];

__device__ __forceinline__ void atomicMaxF(float* addr, float v) {
    if (v >= 0.0f) atomicMax((int*)addr, __float_as_int(v));
    else           atomicMin((unsigned int*)addr, __float_as_uint(v));
}

__device__ __forceinline__ uint32_t smem_u32(const void* p) {
    uint32_t a;
    asm("{ .reg .u64 t; cvta.to.shared.u64 t, %1; cvt.u32.u64 %0, t; }" : "=r"(a) : "l"(p));
    return a;
}

__device__ __forceinline__ void ldsm_x4(uint32_t* r, uint32_t addr) {
    asm volatile("ldmatrix.sync.aligned.m8n8.x4.shared.b16 {%0,%1,%2,%3}, [%4];"
                 : "=r"(r[0]), "=r"(r[1]), "=r"(r[2]), "=r"(r[3]) : "r"(addr));
}

__device__ __forceinline__ void mma16816(float* c, const uint32_t* a, const uint32_t* b) {
    asm volatile("mma.sync.aligned.m16n8k16.row.col.f32.f16.f16.f32 "
                 "{%0,%1,%2,%3}, {%4,%5,%6,%7}, {%8,%9}, {%0,%1,%2,%3};"
                 : "+f"(c[0]), "+f"(c[1]), "+f"(c[2]), "+f"(c[3])
                 : "r"(a[0]), "r"(a[1]), "r"(a[2]), "r"(a[3]), "r"(b[0]), "r"(b[1]));
}

// ---------------- prep: fp16 conversions + softmax init ----------------
__global__ void k_prep(const float* __restrict__ x, const float* __restrict__ We,
                       const float* __restrict__ Wq, const float* __restrict__ Wk,
                       const float* __restrict__ Wv, const float* __restrict__ Ws)
{
    int i = blockIdx.x * blockDim.x + threadIdx.x;
    if (i < Nn * Dd) g_xh[i] = __float2half_rn(x[i]);
    if (i < 128 * 256) {                 // g_Weh[n][k] = We[k][n]
        int n = i >> 8, k = i & 255;
        g_Weh[i] = __float2half_rn(We[k * 128 + n]);
    }
    if (i < 512 * 128) {                 // g_Wallh[j][kk] = Wm[kk][n]
        int j = i >> 7, kk = i & 127;
        int m = j >> 7, n = j & 127;
        const float* W = (m == 0) ? Wq : (m == 1) ? Wk : (m == 2) ? Wv : Ws;
        g_Wallh[i] = __float2half_rn(W[kk * 128 + n]);
    }
    if (i < Nn * 2) { g_amax[i] = -INFINITY; g_denom[i] = 0.0f; }
}

// ---------------- node GEMM: [q|k|v|skip] = x @ [Wq|Wk|Wv|Wskip] ----------------
// smem: sB 512x128 fp16 pitch 136 halfs (139264B), sA 128x128 pitch 136 (34816B)
#define NP 136
#define NODE_A_OFF 139264
#define NODE_SMEM  174080
#define N_TILES    391

__global__ void __launch_bounds__(256, 1) k_node_mma(
    const float* __restrict__ bq, const float* __restrict__ bk,
    const float* __restrict__ bv, const float* __restrict__ bs,
    float* __restrict__ out)
{
    extern __shared__ char sm[];
    uint32_t sbase = smem_u32(sm);
    int tid = threadIdx.x, w = tid >> 5, l = tid & 31;

    // resident B: 512 rows x 128 k
    for (int c = tid; c < 8192; c += 256) {
        int row = c >> 4, kc = c & 15;
        *(uint4*)(sm + row * (NP * 2) + kc * 16) = ((const uint4*)g_Wallh)[c];
    }

    int rg = w >> 1, cg = w & 1;             // rows 32*rg.., cols 64*cg..
    for (int tile = blockIdx.x; tile < N_TILES; tile += gridDim.x) {
        int n0 = tile * 128;
        __syncthreads();
        for (int c = tid; c < 2048; c += 256) {
            int row = c >> 4, kc = c & 15;
            int nr = n0 + row;
            uint4 v = make_uint4(0, 0, 0, 0);
            if (nr < Nn) v = ((const uint4*)g_xh)[((size_t)nr * 128) / 8 + kc];
            *(uint4*)(sm + NODE_A_OFF + row * (NP * 2) + kc * 16) = v;
        }
        __syncthreads();

        for (int mat = 0; mat < 4; mat++) {
            float acc[2][8][4];
#pragma unroll
            for (int mi = 0; mi < 2; mi++)
#pragma unroll
                for (int nb = 0; nb < 8; nb++)
#pragma unroll
                    for (int j = 0; j < 4; j++) acc[mi][nb][j] = 0.0f;

#pragma unroll
            for (int ks = 0; ks < 8; ks++) {
                uint32_t af[2][4];
#pragma unroll
                for (int mi = 0; mi < 2; mi++) {
                    uint32_t addr = sbase + NODE_A_OFF
                        + (uint32_t)(rg * 32 + mi * 16 + (l & 15)) * (NP * 2)
                        + ks * 32 + (l >> 4) * 16;
                    ldsm_x4(af[mi], addr);
                }
                uint32_t bf[8][2];
#pragma unroll
                for (int nbp = 0; nbp < 4; nbp++) {
                    uint32_t r[4];
                    int n = mat * 128 + cg * 64 + nbp * 16 + (l & 7) + ((l >> 4) << 3);
                    uint32_t addr = sbase + (uint32_t)n * (NP * 2)
                        + ks * 32 + ((l >> 3) & 1) * 16;
                    ldsm_x4(r, addr);
                    bf[nbp * 2][0] = r[0]; bf[nbp * 2][1] = r[1];
                    bf[nbp * 2 + 1][0] = r[2]; bf[nbp * 2 + 1][1] = r[3];
                }
#pragma unroll
                for (int mi = 0; mi < 2; mi++)
#pragma unroll
                    for (int nb = 0; nb < 8; nb++)
                        mma16816(acc[mi][nb], af[mi], bf[nb]);
            }

            // epilogue: direct fragment stores
            const float* bias = (mat == 0) ? bq : (mat == 1) ? bk : (mat == 2) ? bv : bs;
#pragma unroll
            for (int mi = 0; mi < 2; mi++) {
                int r0 = n0 + rg * 32 + mi * 16 + (l >> 2);
#pragma unroll
                for (int nb = 0; nb < 8; nb++) {
                    int col = cg * 64 + nb * 8 + 2 * (l & 3);
                    float2 bi = *(const float2*)&bias[col];
                    if (mat == 3) {
                        if (r0 < Nn)
                            *(float2*)&out[(size_t)r0 * 128 + col] =
                                make_float2(acc[mi][nb][0] + bi.x, acc[mi][nb][1] + bi.y);
                        if (r0 + 8 < Nn)
                            *(float2*)&out[(size_t)(r0 + 8) * 128 + col] =
                                make_float2(acc[mi][nb][2] + bi.x, acc[mi][nb][3] + bi.y);
                    } else {
                        __half* dst = (mat == 0) ? g_qh : (mat == 1) ? g_kh : g_vh;
                        if (r0 < Nn)
                            *(__half2*)&dst[(size_t)r0 * 128 + col] =
                                __floats2half2_rn(acc[mi][nb][0] + bi.x, acc[mi][nb][1] + bi.y);
                        if (r0 + 8 < Nn)
                            *(__half2*)&dst[(size_t)(r0 + 8) * 128 + col] =
                                __floats2half2_rn(acc[mi][nb][2] + bi.x, acc[mi][nb][3] + bi.y);
                    }
                }
            }
        }
    }
}

// ---------------- edge GEMM: e = [cos(time)|msg] @ We, alpha, vj ----------------
// smem: sA 128x264 halfs (67584B, overlapped by sC 128x132 f32), sB 128x264 halfs,
// meta at 135168.
#define EPA 264
#define EPC 132
#define E_B_OFF   67584
#define E_META    135168
#define E_WT      (E_META)
#define E_BT      (E_META + 512)
#define E_SRC     (E_META + 1024)
#define E_DST     (E_META + 1536)
#define E_RLT     (E_META + 2048)
#define EDGE_SMEM (E_META + 2560)
#define E_TILES   6250

__global__ void __launch_bounds__(256, 1) k_edge_mma(
    const int*   __restrict__ ei,
    const float* __restrict__ last_update,
    const float* __restrict__ t,
    const float* __restrict__ msg,
    const float* __restrict__ Wt,
    const float* __restrict__ bt)
{
    extern __shared__ char sm[];
    uint32_t sbase = smem_u32(sm);
    int tid = threadIdx.x, w = tid >> 5, l = tid & 31;

    float* sWt = (float*)(sm + E_WT);
    float* sBt = (float*)(sm + E_BT);
    int*   sSrc = (int*)(sm + E_SRC);
    int*   sDst = (int*)(sm + E_DST);
    float* sRlt = (float*)(sm + E_RLT);
    float* sC   = (float*)sm;           // overlaps sA

    if (tid < 128) { sWt[tid] = Wt[tid]; sBt[tid] = bt[tid]; }
    // resident B = g_Weh [128 n][256 k]
    for (int c = tid; c < 4096; c += 256) {
        int row = c >> 5, kc = c & 31;
        *(uint4*)(sm + E_B_OFF + row * (EPA * 2) + kc * 16) = ((const uint4*)g_Weh)[c];
    }

    int rg = w >> 1, cg = w & 1;
    for (int tile = blockIdx.x; tile < E_TILES; tile += gridDim.x) {
        __syncthreads();           // previous epilogue done before overwriting meta/A
        if (tid < 128) {
            int e = tile * 128 + tid;
            int s = ei[e];
            sSrc[tid] = s;
            sDst[tid] = ei[Ee + e];
            sRlt[tid] = last_update[s] - t[e];
        }
        __syncthreads();

        // build A tile [128 edges x 256 k] fp16
#pragma unroll
        for (int p = 0; p < 4; p++) {
            int baseE = p * 32 + (w << 2);
#pragma unroll
            for (int rr = 0; rr < 2; rr++) {
                int el = baseE + rr * 2 + (l >> 4);
                int k0 = (l & 15) * 8;
                float rt = sRlt[el];
                __half2 hv[4];
#pragma unroll
                for (int j = 0; j < 4; j++) {
                    float a0 = cosf(fmaf(rt, sWt[k0 + 2 * j],     sBt[k0 + 2 * j]));
                    float a1 = cosf(fmaf(rt, sWt[k0 + 2 * j + 1], sBt[k0 + 2 * j + 1]));
                    hv[j] = __floats2half2_rn(a0, a1);
                }
                *(uint4*)(sm + el * (EPA * 2) + k0 * 2) = *(uint4*)hv;
            }
            {
                int el = baseE + (l >> 3);
                int km = (l & 7) * 16;
                const float4* mp = (const float4*)(msg + (size_t)(tile * 128 + el) * 128 + km);
                float4 m0 = mp[0], m1 = mp[1], m2 = mp[2], m3 = mp[3];
                __half2 h[8];
                h[0] = __floats2half2_rn(m0.x, m0.y); h[1] = __floats2half2_rn(m0.z, m0.w);
                h[2] = __floats2half2_rn(m1.x, m1.y); h[3] = __floats2half2_rn(m1.z, m1.w);
                h[4] = __floats2half2_rn(m2.x, m2.y); h[5] = __floats2half2_rn(m2.z, m2.w);
                h[6] = __floats2half2_rn(m3.x, m3.y); h[7] = __floats2half2_rn(m3.z, m3.w);
                char* base = sm + el * (EPA * 2) + (256 + km * 2);
                *(uint4*)base        = *(uint4*)&h[0];
                *(uint4*)(base + 16) = *(uint4*)&h[4];
            }
        }
        __syncthreads();

        // MMA: warp tile 32 rows x 64 cols, K=256
        float acc[2][8][4];
#pragma unroll
        for (int mi = 0; mi < 2; mi++)
#pragma unroll
            for (int nb = 0; nb < 8; nb++)
#pragma unroll
                for (int j = 0; j < 4; j++) acc[mi][nb][j] = 0.0f;

#pragma unroll
        for (int ks = 0; ks < 16; ks++) {
            uint32_t af[2][4];
#pragma unroll
            for (int mi = 0; mi < 2; mi++) {
                uint32_t addr = sbase
                    + (uint32_t)(rg * 32 + mi * 16 + (l & 15)) * (EPA * 2)
                    + ks * 32 + (l >> 4) * 16;
                ldsm_x4(af[mi], addr);
            }
            uint32_t bf[8][2];
#pragma unroll
            for (int nbp = 0; nbp < 4; nbp++) {
                uint32_t r[4];
                int n = cg * 64 + nbp * 16 + (l & 7) + ((l >> 4) << 3);
                uint32_t addr = sbase + E_B_OFF + (uint32_t)n * (EPA * 2)
                    + ks * 32 + ((l >> 3) & 1) * 16;
                ldsm_x4(r, addr);
                bf[nbp * 2][0] = r[0]; bf[nbp * 2][1] = r[1];
                bf[nbp * 2 + 1][0] = r[2]; bf[nbp * 2 + 1][1] = r[3];
            }
#pragma unroll
            for (int mi = 0; mi < 2; mi++)
#pragma unroll
                for (int nb = 0; nb < 8; nb++)
                    mma16816(acc[mi][nb], af[mi], bf[nb]);
        }
        __syncthreads();           // all A reads done; stage C over A

#pragma unroll
        for (int mi = 0; mi < 2; mi++) {
            int r0 = rg * 32 + mi * 16 + (l >> 2);
#pragma unroll
            for (int nb = 0; nb < 8; nb++) {
                int col = cg * 64 + nb * 8 + 2 * (l & 3);
                *(float2*)&sC[r0 * EPC + col]       = make_float2(acc[mi][nb][0], acc[mi][nb][1]);
                *(float2*)&sC[(r0 + 8) * EPC + col] = make_float2(acc[mi][nb][2], acc[mi][nb][3]);
            }
        }
        __syncthreads();

        // epilogue: thread -> (edge el, 64-col half hf)
        {
            int sp = w & 3, hf = w >> 2;
            int el = sp * 32 + l;
            int e = tile * 128 + el;
            int s = sSrc[el], d = sDst[el];
            const float4* ep4 = (const float4*)&sC[el * EPC + hf * 64];
            const uint4* qp = (const uint4*)(g_qh + (size_t)d * 128 + hf * 64);
            const uint4* kp = (const uint4*)(g_kh + (size_t)s * 128 + hf * 64);
            const uint4* vp = (const uint4*)(g_vh + (size_t)s * 128 + hf * 64);
            uint4* op = (uint4*)(g_vj + (size_t)e * 128 + hf * 64);

            float dot = 0.0f;
#pragma unroll
            for (int i = 0; i < 8; i++) {
                uint4 qu = qp[i], ku = kp[i], vu = vp[i];
                float4 e0 = ep4[i * 2], e1 = ep4[i * 2 + 1];
                const float* ev = (const float*)&e0;   // e0.xyzw, then e1
                __half2* q2 = (__half2*)&qu;
                __half2* k2 = (__half2*)&ku;
                __half2* v2 = (__half2*)&vu;
                __half2 o2[4];
#pragma unroll
                for (int j = 0; j < 4; j++) {
                    float ea = (j < 2) ? ((float*)&e0)[j * 2]     : ((float*)&e1)[(j - 2) * 2];
                    float eb = (j < 2) ? ((float*)&e0)[j * 2 + 1] : ((float*)&e1)[(j - 2) * 2 + 1];
                    float2 qf = __half22float2(q2[j]);
                    float2 kf = __half22float2(k2[j]);
                    float2 vf = __half22float2(v2[j]);
                    dot = fmaf(qf.x, kf.x + ea, dot);
                    dot = fmaf(qf.y, kf.y + eb, dot);
                    o2[j] = __floats2half2_rn(vf.x + ea, vf.y + eb);
                }
                (void)ev;
                op[i] = *(uint4*)o2;
            }
            float alpha = dot * 0.125f;
            g_alpha[e * 2 + hf] = alpha;
            atomicMaxF(&g_amax[d * 2 + hf], alpha);
        }
    }
}

// ---------------- exp + denominator ----------------
__global__ void k_expsum(const int* __restrict__ ei) {
    int i = blockIdx.x * blockDim.x + threadIdx.x;
    if (i >= Ee * 2) return;
    int e = i >> 1, h = i & 1;
    int d = ei[Ee + e];
    float ex = expf(g_alpha[i] - g_amax[d * 2 + h]);
    g_alpha[i] = ex;
    atomicAdd(&g_denom[d * 2 + h], ex);
}

// ---------------- weighted aggregation (warp per edge) ----------------
__global__ void __launch_bounds__(256) k_agg(const int* __restrict__ ei,
                                             float* __restrict__ out)
{
    int gtid = blockIdx.x * blockDim.x + threadIdx.x;
    int e = gtid >> 5;
    if (e >= Ee) return;
    int lane = threadIdx.x & 31;

    int d = ei[Ee + e];
    float2 ex  = *(const float2*)&g_alpha[e * 2];
    float2 den = *(const float2*)&g_denom[d * 2];
    float wgt = (lane < 16) ? (ex.x / den.x) : (ex.y / den.y);

    int c = lane * 4;
    const __half2* vp = (const __half2*)(g_vj + (size_t)e * 128 + c);
    float2 a = __half22float2(vp[0]);
    float2 b = __half22float2(vp[1]);
    float4 r;
    r.x = wgt * a.x; r.y = wgt * a.y; r.z = wgt * b.x; r.w = wgt * b.y;

    float* p = &out[(size_t)d * 128 + c];
    asm volatile("red.global.add.v4.f32 [%0], {%1, %2, %3, %4};"
                 :: "l"(p), "f"(r.x), "f"(r.y), "f"(r.z), "f"(r.w)
                 : "memory");
}

// ---------------- launch ----------------
extern "C" void kernel_launch(void* const* d_in, const int* in_sizes, int n_in,
                              void* d_out, int out_size)
{
    const float* x           = (const float*)d_in[0];
    const float* last_update = (const float*)d_in[1];
    const int*   ei          = (const int*)  d_in[2];
    const float* t           = (const float*)d_in[3];
    const float* msg         = (const float*)d_in[4];
    const float* Wt          = (const float*)d_in[5];
    const float* bt          = (const float*)d_in[6];
    const float* Wq          = (const float*)d_in[7];
    const float* bq          = (const float*)d_in[8];
    const float* Wk          = (const float*)d_in[9];
    const float* bk          = (const float*)d_in[10];
    const float* Wv          = (const float*)d_in[11];
    const float* bv          = (const float*)d_in[12];
    const float* We          = (const float*)d_in[13];
    const float* Wskip       = (const float*)d_in[14];
    const float* bskip       = (const float*)d_in[15];
    float* out = (float*)d_out;

    cudaFuncSetAttribute(k_node_mma, cudaFuncAttributeMaxDynamicSharedMemorySize, NODE_SMEM);
    cudaFuncSetAttribute(k_edge_mma, cudaFuncAttributeMaxDynamicSharedMemorySize, EDGE_SMEM);

    k_prep<<<(Nn * Dd + 255) / 256, 256>>>(x, We, Wq, Wk, Wv, Wskip);

    k_node_mma<<<148, 256, NODE_SMEM>>>(bq, bk, bv, bskip, out);

    k_edge_mma<<<148, 256, EDGE_SMEM>>>(ei, last_update, t, msg, Wt, bt);

    k_expsum<<<(Ee * 2 + 255) / 256, 256>>>(ei);

    k_agg<<<(Ee * 32 + 255) / 256, 256>>>(ei, out);
}

// round 5
// speedup vs baseline: 2.9477x; 1.5937x over previous
#include <cuda_runtime.h>
#include <cuda_fp16.h>
#include <cstdint>
#include <math.h>

#define Nn 50000
#define Ee 800000
#define Dd 128

#define TABN 65536
#define TH0  (-1000.0f)
#define HSTEP   (2000.0f / 65535.0f)
#define TSCALE  (65535.0f / 2000.0f)

// ---------------- scratch (static device globals; no allocation) ----------------
__device__ __half g_xh[(size_t)Nn * Dd];
__device__ __half g_qh[(size_t)Nn * Dd];
__device__ __half g_kh[(size_t)Nn * Dd];
__device__ __half g_vh[(size_t)Nn * Dd];
__device__ __half g_Weth[128 * 128];       // [n][k] fp16: We_top^T (time-enc rows)
__device__ __half g_Webh[128 * 128];       // [n][k] fp16: We_bot^T (msg rows)
__device__ __half g_Wallh[512 * 128];      // [j][k], j = {q|k|v|skip}*128+n
__device__ __half g_tab[(size_t)TABN * 128]; // g(theta) table, fp16 (16.8MB, L2-resident)
__device__ __half g_vj[(size_t)Ee * Dd];   // v[src]+e, fp16 (205MB)
__device__ float  g_alpha[Ee * 2];
__device__ float  g_amax[Nn * 2];
__device__ float  g_denom[Nn * 2];

__device__ __forceinline__ void atomicMaxF(float* addr, float v) {
    if (v >= 0.0f) atomicMax((int*)addr, __float_as_int(v));
    else           atomicMin((unsigned int*)addr, __float_as_uint(v));
}

__device__ __forceinline__ uint32_t smem_u32(const void* p) {
    uint32_t a;
    asm("{ .reg .u64 t; cvta.to.shared.u64 t, %1; cvt.u32.u64 %0, t; }" : "=r"(a) : "l"(p));
    return a;
}

__device__ __forceinline__ void ldsm_x4(uint32_t* r, uint32_t addr) {
    asm volatile("ldmatrix.sync.aligned.m8n8.x4.shared.b16 {%0,%1,%2,%3}, [%4];"
                 : "=r"(r[0]), "=r"(r[1]), "=r"(r[2]), "=r"(r[3]) : "r"(addr));
}

__device__ __forceinline__ void mma16816(float* c, const uint32_t* a, const uint32_t* b) {
    asm volatile("mma.sync.aligned.m16n8k16.row.col.f32.f16.f16.f32 "
                 "{%0,%1,%2,%3}, {%4,%5,%6,%7}, {%8,%9}, {%0,%1,%2,%3};"
                 : "+f"(c[0]), "+f"(c[1]), "+f"(c[2]), "+f"(c[3])
                 : "r"(a[0]), "r"(a[1]), "r"(a[2]), "r"(a[3]), "r"(b[0]), "r"(b[1]));
}

// ---------------- prep: fp16 conversions + softmax init ----------------
__global__ void k_prep(const float* __restrict__ x, const float* __restrict__ We,
                       const float* __restrict__ Wq, const float* __restrict__ Wk,
                       const float* __restrict__ Wv, const float* __restrict__ Ws)
{
    int i = blockIdx.x * blockDim.x + threadIdx.x;
    if (i < Nn * Dd) g_xh[i] = __float2half_rn(x[i]);
    if (i < 128 * 128) {                 // transposed We halves
        int n = i >> 7, k = i & 127;
        g_Weth[i] = __float2half_rn(We[k * 128 + n]);
        g_Webh[i] = __float2half_rn(We[(k + 128) * 128 + n]);
    }
    if (i < 512 * 128) {                 // g_Wallh[j][kk] = Wm[kk][n]
        int j = i >> 7, kk = i & 127;
        int m = j >> 7, n = j & 127;
        const float* W = (m == 0) ? Wq : (m == 1) ? Wk : (m == 2) ? Wv : Ws;
        g_Wallh[i] = __float2half_rn(W[kk * 128 + n]);
    }
    if (i < Nn * 2) { g_amax[i] = -INFINITY; g_denom[i] = 0.0f; }
}

// ---------------- table build: g_tab[i][:] = cos(theta_i*Wt+bt) @ We_top ----------------
// smem: sA 128x136h (34816B), sB 128x136h (34816B), Wt 512B, bt 512B
#define TB_B_OFF 34816
#define TB_WT    69632
#define TB_BT    70144
#define TB_SMEM  70656
#define TB_TILES (TABN / 128)

__global__ void __launch_bounds__(256, 1) k_table(const float* __restrict__ Wt,
                                                  const float* __restrict__ bt)
{
    extern __shared__ char sm[];
    uint32_t sbase = smem_u32(sm);
    int tid = threadIdx.x, w = tid >> 5, l = tid & 31;
    float* sWt = (float*)(sm + TB_WT);
    float* sBt = (float*)(sm + TB_BT);

    if (tid < 128) { sWt[tid] = Wt[tid]; sBt[tid] = bt[tid]; }
    for (int c = tid; c < 2048; c += 256) {
        int row = c >> 4, kc = c & 15;
        *(uint4*)(sm + TB_B_OFF + row * 272 + kc * 16) = ((const uint4*)g_Weth)[c];
    }

    int rg = w >> 1, cg = w & 1;
    for (int tile = blockIdx.x; tile < TB_TILES; tile += gridDim.x) {
        __syncthreads();
        // build cos tile: 128 rows (theta) x 128 k
        for (int idx = tid; idx < 8192; idx += 256) {
            int row = idx >> 6, k2 = (idx & 63) * 2;
            float th = TH0 + (float)(tile * 128 + row) * HSTEP;
            float a0 = cosf(fmaf(th, sWt[k2],     sBt[k2]));
            float a1 = cosf(fmaf(th, sWt[k2 + 1], sBt[k2 + 1]));
            *(__half2*)(sm + row * 272 + k2 * 2) = __floats2half2_rn(a0, a1);
        }
        __syncthreads();

        float acc[2][8][4];
#pragma unroll
        for (int mi = 0; mi < 2; mi++)
#pragma unroll
            for (int nb = 0; nb < 8; nb++)
#pragma unroll
                for (int j = 0; j < 4; j++) acc[mi][nb][j] = 0.0f;

#pragma unroll
        for (int ks = 0; ks < 8; ks++) {
            uint32_t af[2][4];
#pragma unroll
            for (int mi = 0; mi < 2; mi++) {
                uint32_t addr = sbase + (uint32_t)(rg * 32 + mi * 16 + (l & 15)) * 272
                              + ks * 32 + (l >> 4) * 16;
                ldsm_x4(af[mi], addr);
            }
            uint32_t bf[8][2];
#pragma unroll
            for (int nbp = 0; nbp < 4; nbp++) {
                uint32_t r[4];
                int n = cg * 64 + nbp * 16 + (l & 7) + ((l >> 4) << 3);
                uint32_t addr = sbase + TB_B_OFF + (uint32_t)n * 272
                              + ks * 32 + ((l >> 3) & 1) * 16;
                ldsm_x4(r, addr);
                bf[nbp * 2][0] = r[0]; bf[nbp * 2][1] = r[1];
                bf[nbp * 2 + 1][0] = r[2]; bf[nbp * 2 + 1][1] = r[3];
            }
#pragma unroll
            for (int mi = 0; mi < 2; mi++)
#pragma unroll
                for (int nb = 0; nb < 8; nb++)
                    mma16816(acc[mi][nb], af[mi], bf[nb]);
        }

        // direct fragment store (fp16)
#pragma unroll
        for (int mi = 0; mi < 2; mi++) {
            int r0 = tile * 128 + rg * 32 + mi * 16 + (l >> 2);
#pragma unroll
            for (int nb = 0; nb < 8; nb++) {
                int col = cg * 64 + nb * 8 + 2 * (l & 3);
                *(__half2*)&g_tab[(size_t)r0 * 128 + col] =
                    __floats2half2_rn(acc[mi][nb][0], acc[mi][nb][1]);
                *(__half2*)&g_tab[(size_t)(r0 + 8) * 128 + col] =
                    __floats2half2_rn(acc[mi][nb][2], acc[mi][nb][3]);
            }
        }
    }
}

// ---------------- node GEMM: [q|k|v|skip] = x @ [Wq|Wk|Wv|Wskip] ----------------
#define NP 136
#define NODE_A_OFF 139264
#define NODE_SMEM  174080
#define N_TILES    391

__global__ void __launch_bounds__(256, 1) k_node_mma(
    const float* __restrict__ bq, const float* __restrict__ bk,
    const float* __restrict__ bv, const float* __restrict__ bs,
    float* __restrict__ out)
{
    extern __shared__ char sm[];
    uint32_t sbase = smem_u32(sm);
    int tid = threadIdx.x, w = tid >> 5, l = tid & 31;

    for (int c = tid; c < 8192; c += 256) {
        int row = c >> 4, kc = c & 15;
        *(uint4*)(sm + row * (NP * 2) + kc * 16) = ((const uint4*)g_Wallh)[c];
    }

    int rg = w >> 1, cg = w & 1;
    for (int tile = blockIdx.x; tile < N_TILES; tile += gridDim.x) {
        int n0 = tile * 128;
        __syncthreads();
        for (int c = tid; c < 2048; c += 256) {
            int row = c >> 4, kc = c & 15;
            int nr = n0 + row;
            uint4 v = make_uint4(0, 0, 0, 0);
            if (nr < Nn) v = ((const uint4*)g_xh)[((size_t)nr * 128) / 8 + kc];
            *(uint4*)(sm + NODE_A_OFF + row * (NP * 2) + kc * 16) = v;
        }
        __syncthreads();

        for (int mat = 0; mat < 4; mat++) {
            float acc[2][8][4];
#pragma unroll
            for (int mi = 0; mi < 2; mi++)
#pragma unroll
                for (int nb = 0; nb < 8; nb++)
#pragma unroll
                    for (int j = 0; j < 4; j++) acc[mi][nb][j] = 0.0f;

#pragma unroll
            for (int ks = 0; ks < 8; ks++) {
                uint32_t af[2][4];
#pragma unroll
                for (int mi = 0; mi < 2; mi++) {
                    uint32_t addr = sbase + NODE_A_OFF
                        + (uint32_t)(rg * 32 + mi * 16 + (l & 15)) * (NP * 2)
                        + ks * 32 + (l >> 4) * 16;
                    ldsm_x4(af[mi], addr);
                }
                uint32_t bf[8][2];
#pragma unroll
                for (int nbp = 0; nbp < 4; nbp++) {
                    uint32_t r[4];
                    int n = mat * 128 + cg * 64 + nbp * 16 + (l & 7) + ((l >> 4) << 3);
                    uint32_t addr = sbase + (uint32_t)n * (NP * 2)
                        + ks * 32 + ((l >> 3) & 1) * 16;
                    ldsm_x4(r, addr);
                    bf[nbp * 2][0] = r[0]; bf[nbp * 2][1] = r[1];
                    bf[nbp * 2 + 1][0] = r[2]; bf[nbp * 2 + 1][1] = r[3];
                }
#pragma unroll
                for (int mi = 0; mi < 2; mi++)
#pragma unroll
                    for (int nb = 0; nb < 8; nb++)
                        mma16816(acc[mi][nb], af[mi], bf[nb]);
            }

            const float* bias = (mat == 0) ? bq : (mat == 1) ? bk : (mat == 2) ? bv : bs;
#pragma unroll
            for (int mi = 0; mi < 2; mi++) {
                int r0 = n0 + rg * 32 + mi * 16 + (l >> 2);
#pragma unroll
                for (int nb = 0; nb < 8; nb++) {
                    int col = cg * 64 + nb * 8 + 2 * (l & 3);
                    float2 bi = *(const float2*)&bias[col];
                    if (mat == 3) {
                        if (r0 < Nn)
                            *(float2*)&out[(size_t)r0 * 128 + col] =
                                make_float2(acc[mi][nb][0] + bi.x, acc[mi][nb][1] + bi.y);
                        if (r0 + 8 < Nn)
                            *(float2*)&out[(size_t)(r0 + 8) * 128 + col] =
                                make_float2(acc[mi][nb][2] + bi.x, acc[mi][nb][3] + bi.y);
                    } else {
                        __half* dst = (mat == 0) ? g_qh : (mat == 1) ? g_kh : g_vh;
                        if (r0 < Nn)
                            *(__half2*)&dst[(size_t)r0 * 128 + col] =
                                __floats2half2_rn(acc[mi][nb][0] + bi.x, acc[mi][nb][1] + bi.y);
                        if (r0 + 8 < Nn)
                            *(__half2*)&dst[(size_t)(r0 + 8) * 128 + col] =
                                __floats2half2_rn(acc[mi][nb][2] + bi.x, acc[mi][nb][3] + bi.y);
                    }
                }
            }
        }
    }
}

// ---------------- edge GEMM: e = msg @ We_bot + table(rel_t); alpha, vj ----------------
// smem: sA/sC 128x136h (34816B), sB 128x136h, src/dst/rlt meta
#define E_B_OFF   34816
#define E_SRC     69632
#define E_DST     70144
#define E_RLT     70656
#define EDGE_SMEM 71168
#define E_TILES   (Ee / 128)

__global__ void __launch_bounds__(256, 1) k_edge_mma(
    const int*   __restrict__ ei,
    const float* __restrict__ last_update,
    const float* __restrict__ t,
    const float* __restrict__ msg)
{
    extern __shared__ char sm[];
    uint32_t sbase = smem_u32(sm);
    int tid = threadIdx.x, w = tid >> 5, l = tid & 31;

    int*   sSrc = (int*)(sm + E_SRC);
    int*   sDst = (int*)(sm + E_DST);
    float* sRlt = (float*)(sm + E_RLT);

    for (int c = tid; c < 2048; c += 256) {
        int row = c >> 4, kc = c & 15;
        *(uint4*)(sm + E_B_OFF + row * 272 + kc * 16) = ((const uint4*)g_Webh)[c];
    }

    int rg = w >> 1, cg = w & 1;
    for (int tile = blockIdx.x; tile < E_TILES; tile += gridDim.x) {
        __syncthreads();           // previous epilogue done before overwriting meta/A
        if (tid < 128) {
            int e = tile * 128 + tid;
            int s = ei[e];
            sSrc[tid] = s;
            sDst[tid] = ei[Ee + e];
            sRlt[tid] = last_update[s] - t[e];
        }
        // build A = msg tile fp16 (no sync needed between meta write and A build: disjoint smem,
        // but meta is read in epilogue after a later sync)
        for (int c = tid; c < 2048; c += 256) {
            int row = c >> 4, kc = c & 15;
            const float4* mp = (const float4*)(msg + (size_t)(tile * 128 + row) * 128 + kc * 8);
            float4 m0 = mp[0], m1 = mp[1];
            __half2 h[4];
            h[0] = __floats2half2_rn(m0.x, m0.y); h[1] = __floats2half2_rn(m0.z, m0.w);
            h[2] = __floats2half2_rn(m1.x, m1.y); h[3] = __floats2half2_rn(m1.z, m1.w);
            *(uint4*)(sm + row * 272 + kc * 16) = *(uint4*)h;
        }
        __syncthreads();

        float acc[2][8][4];
#pragma unroll
        for (int mi = 0; mi < 2; mi++)
#pragma unroll
            for (int nb = 0; nb < 8; nb++)
#pragma unroll
                for (int j = 0; j < 4; j++) acc[mi][nb][j] = 0.0f;

#pragma unroll
        for (int ks = 0; ks < 8; ks++) {
            uint32_t af[2][4];
#pragma unroll
            for (int mi = 0; mi < 2; mi++) {
                uint32_t addr = sbase + (uint32_t)(rg * 32 + mi * 16 + (l & 15)) * 272
                              + ks * 32 + (l >> 4) * 16;
                ldsm_x4(af[mi], addr);
            }
            uint32_t bf[8][2];
#pragma unroll
            for (int nbp = 0; nbp < 4; nbp++) {
                uint32_t r[4];
                int n = cg * 64 + nbp * 16 + (l & 7) + ((l >> 4) << 3);
                uint32_t addr = sbase + E_B_OFF + (uint32_t)n * 272
                              + ks * 32 + ((l >> 3) & 1) * 16;
                ldsm_x4(r, addr);
                bf[nbp * 2][0] = r[0]; bf[nbp * 2][1] = r[1];
                bf[nbp * 2 + 1][0] = r[2]; bf[nbp * 2 + 1][1] = r[3];
            }
#pragma unroll
            for (int mi = 0; mi < 2; mi++)
#pragma unroll
                for (int nb = 0; nb < 8; nb++)
                    mma16816(acc[mi][nb], af[mi], bf[nb]);
        }
        __syncthreads();           // all A reads done; stage C (fp16) over A

#pragma unroll
        for (int mi = 0; mi < 2; mi++) {
            int r0 = rg * 32 + mi * 16 + (l >> 2);
#pragma unroll
            for (int nb = 0; nb < 8; nb++) {
                int col = cg * 64 + nb * 8 + 2 * (l & 3);
                *(__half2*)(sm + r0 * 272 + col * 2) =
                    __floats2half2_rn(acc[mi][nb][0], acc[mi][nb][1]);
                *(__half2*)(sm + (r0 + 8) * 272 + col * 2) =
                    __floats2half2_rn(acc[mi][nb][2], acc[mi][nb][3]);
            }
        }
        __syncthreads();

        // epilogue: thread -> (edge el, 64-col half hf)
        {
            int sp = w & 3, hf = w >> 2;
            int el = sp * 32 + l;
            int e = tile * 128 + el;
            int s = sSrc[el], d = sDst[el];

            float f = (sRlt[el] - TH0) * TSCALE;
            int i0 = (int)f;
            i0 = max(0, min(i0, TABN - 2));
            float fr = f - (float)i0;

            const uint4* t0p = (const uint4*)(g_tab + (size_t)i0 * 128 + hf * 64);
            const uint4* t1p = (const uint4*)(g_tab + (size_t)(i0 + 1) * 128 + hf * 64);
            const uint4* cp  = (const uint4*)(sm + el * 272 + hf * 128);
            const uint4* qp = (const uint4*)(g_qh + (size_t)d * 128 + hf * 64);
            const uint4* kp = (const uint4*)(g_kh + (size_t)s * 128 + hf * 64);
            const uint4* vp = (const uint4*)(g_vh + (size_t)s * 128 + hf * 64);
            uint4* op = (uint4*)(g_vj + (size_t)e * 128 + hf * 64);

            float dot = 0.0f;
#pragma unroll
            for (int i = 0; i < 8; i++) {
                uint4 qu = qp[i], ku = kp[i], vu = vp[i];
                uint4 cu = cp[i], g0u = t0p[i], g1u = t1p[i];
                __half2* q2 = (__half2*)&qu;
                __half2* k2 = (__half2*)&ku;
                __half2* v2 = (__half2*)&vu;
                __half2* c2 = (__half2*)&cu;
                __half2* g02 = (__half2*)&g0u;
                __half2* g12 = (__half2*)&g1u;
                __half2 o2[4];
#pragma unroll
                for (int j = 0; j < 4; j++) {
                    float2 cf = __half22float2(c2[j]);
                    float2 ga = __half22float2(g02[j]);
                    float2 gb = __half22float2(g12[j]);
                    float ea = cf.x + ga.x + fr * (gb.x - ga.x);
                    float eb = cf.y + ga.y + fr * (gb.y - ga.y);
                    float2 qf = __half22float2(q2[j]);
                    float2 kf = __half22float2(k2[j]);
                    float2 vf = __half22float2(v2[j]);
                    dot = fmaf(qf.x, kf.x + ea, dot);
                    dot = fmaf(qf.y, kf.y + eb, dot);
                    o2[j] = __floats2half2_rn(vf.x + ea, vf.y + eb);
                }
                op[i] = *(uint4*)o2;
            }
            float alpha = dot * 0.125f;
            g_alpha[e * 2 + hf] = alpha;
            atomicMaxF(&g_amax[d * 2 + hf], alpha);
        }
    }
}

// ---------------- exp + denominator ----------------
__global__ void k_expsum(const int* __restrict__ ei) {
    int i = blockIdx.x * blockDim.x + threadIdx.x;
    if (i >= Ee * 2) return;
    int e = i >> 1, h = i & 1;
    int d = ei[Ee + e];
    float ex = expf(g_alpha[i] - g_amax[d * 2 + h]);
    g_alpha[i] = ex;
    atomicAdd(&g_denom[d * 2 + h], ex);
}

// ---------------- weighted aggregation (warp per edge) ----------------
__global__ void __launch_bounds__(256) k_agg(const int* __restrict__ ei,
                                             float* __restrict__ out)
{
    int gtid = blockIdx.x * blockDim.x + threadIdx.x;
    int e = gtid >> 5;
    if (e >= Ee) return;
    int lane = threadIdx.x & 31;

    int d = ei[Ee + e];
    float2 ex  = *(const float2*)&g_alpha[e * 2];
    float2 den = *(const float2*)&g_denom[d * 2];
    float wgt = (lane < 16) ? (ex.x / den.x) : (ex.y / den.y);

    int c = lane * 4;
    const __half2* vp = (const __half2*)(g_vj + (size_t)e * 128 + c);
    float2 a = __half22float2(vp[0]);
    float2 b = __half22float2(vp[1]);
    float4 r;
    r.x = wgt * a.x; r.y = wgt * a.y; r.z = wgt * b.x; r.w = wgt * b.y;

    float* p = &out[(size_t)d * 128 + c];
    asm volatile("red.global.add.v4.f32 [%0], {%1, %2, %3, %4};"
                 :: "l"(p), "f"(r.x), "f"(r.y), "f"(r.z), "f"(r.w)
                 : "memory");
}

// ---------------- launch ----------------
extern "C" void kernel_launch(void* const* d_in, const int* in_sizes, int n_in,
                              void* d_out, int out_size)
{
    const float* x           = (const float*)d_in[0];
    const float* last_update = (const float*)d_in[1];
    const int*   ei          = (const int*)  d_in[2];
    const float* t           = (const float*)d_in[3];
    const float* msg         = (const float*)d_in[4];
    const float* Wt          = (const float*)d_in[5];
    const float* bt          = (const float*)d_in[6];
    const float* Wq          = (const float*)d_in[7];
    const float* bq          = (const float*)d_in[8];
    const float* Wk          = (const float*)d_in[9];
    const float* bk          = (const float*)d_in[10];
    const float* Wv          = (const float*)d_in[11];
    const float* bv          = (const float*)d_in[12];
    const float* We          = (const float*)d_in[13];
    const float* Wskip       = (const float*)d_in[14];
    const float* bskip       = (const float*)d_in[15];
    float* out = (float*)d_out;

    cudaFuncSetAttribute(k_table,    cudaFuncAttributeMaxDynamicSharedMemorySize, TB_SMEM);
    cudaFuncSetAttribute(k_node_mma, cudaFuncAttributeMaxDynamicSharedMemorySize, NODE_SMEM);
    cudaFuncSetAttribute(k_edge_mma, cudaFuncAttributeMaxDynamicSharedMemorySize, EDGE_SMEM);

    k_prep<<<(Nn * Dd + 255) / 256, 256>>>(x, We, Wq, Wk, Wv, Wskip);

    k_table<<<148, 256, TB_SMEM>>>(Wt, bt);

    k_node_mma<<<148, 256, NODE_SMEM>>>(bq, bk, bv, bskip, out);

    k_edge_mma<<<148, 256, EDGE_SMEM>>>(ei, last_update, t, msg);

    k_expsum<<<(Ee * 2 + 255) / 256, 256>>>(ei);

    k_agg<<<(Ee * 32 + 255) / 256, 256>>>(ei, out);
}

// round 6
// speedup vs baseline: 3.1420x; 1.0659x over previous
#include <cuda_runtime.h>
#include <cuda_fp16.h>
#include <cstdint>
#include <math.h>

#define Nn 50000
#define Ee 800000
#define Dd 128

#define TABN 65536
#define TH0  (-1000.0f)
#define HSTEP   (2000.0f / 65535.0f)
#define TSCALE  (65535.0f / 2000.0f)

// ---------------- scratch (static device globals; no allocation) ----------------
__device__ __half g_xh[(size_t)Nn * Dd];
__device__ __half g_qh[(size_t)Nn * Dd];
__device__ __half g_kh[(size_t)Nn * Dd];
__device__ __half g_vh[(size_t)Nn * Dd];
__device__ __half g_Weth[128 * 128];       // [n][k] fp16: We_top^T (time-enc rows)
__device__ __half g_Webh[128 * 128];       // [n][k] fp16: We_bot^T (msg rows)
__device__ __half g_Wallh[512 * 128];      // [j][k], j = {q|k|v|skip}*128+n
__device__ __half g_tab[(size_t)TABN * 128]; // g(theta) table, fp16 (16.8MB)
__device__ __half g_vj[(size_t)Ee * Dd];   // v[src]+e, fp16 (205MB)
__device__ float  g_alpha[Ee * 2];
__device__ float  g_amax[Nn * 2];
__device__ float  g_denom[Nn * 2];

__device__ __forceinline__ void atomicMaxF(float* addr, float v) {
    if (v >= 0.0f) atomicMax((int*)addr, __float_as_int(v));
    else           atomicMin((unsigned int*)addr, __float_as_uint(v));
}

__device__ __forceinline__ uint32_t smem_u32(const void* p) {
    uint32_t a;
    asm("{ .reg .u64 t; cvta.to.shared.u64 t, %1; cvt.u32.u64 %0, t; }" : "=r"(a) : "l"(p));
    return a;
}

__device__ __forceinline__ void ldsm_x4(uint32_t* r, uint32_t addr) {
    asm volatile("ldmatrix.sync.aligned.m8n8.x4.shared.b16 {%0,%1,%2,%3}, [%4];"
                 : "=r"(r[0]), "=r"(r[1]), "=r"(r[2]), "=r"(r[3]) : "r"(addr));
}

__device__ __forceinline__ void mma16816(float* c, const uint32_t* a, const uint32_t* b) {
    asm volatile("mma.sync.aligned.m16n8k16.row.col.f32.f16.f16.f32 "
                 "{%0,%1,%2,%3}, {%4,%5,%6,%7}, {%8,%9}, {%0,%1,%2,%3};"
                 : "+f"(c[0]), "+f"(c[1]), "+f"(c[2]), "+f"(c[3])
                 : "r"(a[0]), "r"(a[1]), "r"(a[2]), "r"(a[3]), "r"(b[0]), "r"(b[1]));
}

// ---------------- prep: fp16 conversions + softmax init ----------------
__global__ void k_prep(const float* __restrict__ x, const float* __restrict__ We,
                       const float* __restrict__ Wq, const float* __restrict__ Wk,
                       const float* __restrict__ Wv, const float* __restrict__ Ws)
{
    int i = blockIdx.x * blockDim.x + threadIdx.x;
    if (i < Nn * Dd) g_xh[i] = __float2half_rn(x[i]);
    if (i < 128 * 128) {                 // transposed We halves
        int n = i >> 7, k = i & 127;
        g_Weth[i] = __float2half_rn(We[k * 128 + n]);
        g_Webh[i] = __float2half_rn(We[(k + 128) * 128 + n]);
    }
    if (i < 512 * 128) {                 // g_Wallh[j][kk] = Wm[kk][n]
        int j = i >> 7, kk = i & 127;
        int m = j >> 7, n = j & 127;
        const float* W = (m == 0) ? Wq : (m == 1) ? Wk : (m == 2) ? Wv : Ws;
        g_Wallh[i] = __float2half_rn(W[kk * 128 + n]);
    }
    if (i < Nn * 2) { g_amax[i] = -INFINITY; g_denom[i] = 0.0f; }
}

// ---------------- table build: g_tab[i][:] = cos(theta_i*Wt+bt) @ We_top ----------------
#define TB_B_OFF 34816
#define TB_WT    69632
#define TB_BT    70144
#define TB_SMEM  70656
#define TB_TILES (TABN / 128)

__global__ void __launch_bounds__(256, 2) k_table(const float* __restrict__ Wt,
                                                  const float* __restrict__ bt)
{
    extern __shared__ char sm[];
    uint32_t sbase = smem_u32(sm);
    int tid = threadIdx.x, w = tid >> 5, l = tid & 31;
    float* sWt = (float*)(sm + TB_WT);
    float* sBt = (float*)(sm + TB_BT);

    if (tid < 128) { sWt[tid] = Wt[tid]; sBt[tid] = bt[tid]; }
    for (int c = tid; c < 2048; c += 256) {
        int row = c >> 4, kc = c & 15;
        *(uint4*)(sm + TB_B_OFF + row * 272 + kc * 16) = ((const uint4*)g_Weth)[c];
    }

    int rg = w >> 1, cg = w & 1;
    for (int tile = blockIdx.x; tile < TB_TILES; tile += gridDim.x) {
        __syncthreads();
        for (int idx = tid; idx < 8192; idx += 256) {
            int row = idx >> 6, k2 = (idx & 63) * 2;
            float th = TH0 + (float)(tile * 128 + row) * HSTEP;
            float a0 = cosf(fmaf(th, sWt[k2],     sBt[k2]));
            float a1 = cosf(fmaf(th, sWt[k2 + 1], sBt[k2 + 1]));
            *(__half2*)(sm + row * 272 + k2 * 2) = __floats2half2_rn(a0, a1);
        }
        __syncthreads();

        float acc[2][8][4];
#pragma unroll
        for (int mi = 0; mi < 2; mi++)
#pragma unroll
            for (int nb = 0; nb < 8; nb++)
#pragma unroll
                for (int j = 0; j < 4; j++) acc[mi][nb][j] = 0.0f;

#pragma unroll
        for (int ks = 0; ks < 8; ks++) {
            uint32_t af[2][4];
#pragma unroll
            for (int mi = 0; mi < 2; mi++) {
                uint32_t addr = sbase + (uint32_t)(rg * 32 + mi * 16 + (l & 15)) * 272
                              + ks * 32 + (l >> 4) * 16;
                ldsm_x4(af[mi], addr);
            }
            uint32_t bf[8][2];
#pragma unroll
            for (int nbp = 0; nbp < 4; nbp++) {
                uint32_t r[4];
                int n = cg * 64 + nbp * 16 + (l & 7) + ((l >> 4) << 3);
                uint32_t addr = sbase + TB_B_OFF + (uint32_t)n * 272
                              + ks * 32 + ((l >> 3) & 1) * 16;
                ldsm_x4(r, addr);
                bf[nbp * 2][0] = r[0]; bf[nbp * 2][1] = r[1];
                bf[nbp * 2 + 1][0] = r[2]; bf[nbp * 2 + 1][1] = r[3];
            }
#pragma unroll
            for (int mi = 0; mi < 2; mi++)
#pragma unroll
                for (int nb = 0; nb < 8; nb++)
                    mma16816(acc[mi][nb], af[mi], bf[nb]);
        }

#pragma unroll
        for (int mi = 0; mi < 2; mi++) {
            int r0 = tile * 128 + rg * 32 + mi * 16 + (l >> 2);
#pragma unroll
            for (int nb = 0; nb < 8; nb++) {
                int col = cg * 64 + nb * 8 + 2 * (l & 3);
                *(__half2*)&g_tab[(size_t)r0 * 128 + col] =
                    __floats2half2_rn(acc[mi][nb][0], acc[mi][nb][1]);
                *(__half2*)&g_tab[(size_t)(r0 + 8) * 128 + col] =
                    __floats2half2_rn(acc[mi][nb][2], acc[mi][nb][3]);
            }
        }
    }
}

// ---------------- node GEMM: blockIdx.y selects matrix; B = one 128x128 weight ----------------
#define NODE_B_OFF 34816
#define NODE_SMEM  69632
#define N_TILES    391

__global__ void __launch_bounds__(256, 2) k_node_mma(
    const float* __restrict__ bq, const float* __restrict__ bk,
    const float* __restrict__ bv, const float* __restrict__ bs,
    float* __restrict__ out)
{
    extern __shared__ char sm[];
    uint32_t sbase = smem_u32(sm);
    int tid = threadIdx.x, w = tid >> 5, l = tid & 31;
    int mat = blockIdx.y;

    const __half* Wsrc = g_Wallh + (size_t)mat * 128 * 128;
    for (int c = tid; c < 2048; c += 256) {
        int row = c >> 4, kc = c & 15;
        *(uint4*)(sm + NODE_B_OFF + row * 272 + kc * 16) = ((const uint4*)Wsrc)[c];
    }

    int rg = w >> 1, cg = w & 1;
    for (int tile = blockIdx.x; tile < N_TILES; tile += gridDim.x) {
        int n0 = tile * 128;
        __syncthreads();
        for (int c = tid; c < 2048; c += 256) {
            int row = c >> 4, kc = c & 15;
            int nr = n0 + row;
            uint4 v = make_uint4(0, 0, 0, 0);
            if (nr < Nn) v = ((const uint4*)g_xh)[((size_t)nr * 128) / 8 + kc];
            *(uint4*)(sm + row * 272 + kc * 16) = v;
        }
        __syncthreads();

        float acc[2][8][4];
#pragma unroll
        for (int mi = 0; mi < 2; mi++)
#pragma unroll
            for (int nb = 0; nb < 8; nb++)
#pragma unroll
                for (int j = 0; j < 4; j++) acc[mi][nb][j] = 0.0f;

#pragma unroll
        for (int ks = 0; ks < 8; ks++) {
            uint32_t af[2][4];
#pragma unroll
            for (int mi = 0; mi < 2; mi++) {
                uint32_t addr = sbase + (uint32_t)(rg * 32 + mi * 16 + (l & 15)) * 272
                              + ks * 32 + (l >> 4) * 16;
                ldsm_x4(af[mi], addr);
            }
            uint32_t bf[8][2];
#pragma unroll
            for (int nbp = 0; nbp < 4; nbp++) {
                uint32_t r[4];
                int n = cg * 64 + nbp * 16 + (l & 7) + ((l >> 4) << 3);
                uint32_t addr = sbase + NODE_B_OFF + (uint32_t)n * 272
                              + ks * 32 + ((l >> 3) & 1) * 16;
                ldsm_x4(r, addr);
                bf[nbp * 2][0] = r[0]; bf[nbp * 2][1] = r[1];
                bf[nbp * 2 + 1][0] = r[2]; bf[nbp * 2 + 1][1] = r[3];
            }
#pragma unroll
            for (int mi = 0; mi < 2; mi++)
#pragma unroll
                for (int nb = 0; nb < 8; nb++)
                    mma16816(acc[mi][nb], af[mi], bf[nb]);
        }

        const float* bias = (mat == 0) ? bq : (mat == 1) ? bk : (mat == 2) ? bv : bs;
#pragma unroll
        for (int mi = 0; mi < 2; mi++) {
            int r0 = n0 + rg * 32 + mi * 16 + (l >> 2);
#pragma unroll
            for (int nb = 0; nb < 8; nb++) {
                int col = cg * 64 + nb * 8 + 2 * (l & 3);
                float2 bi = *(const float2*)&bias[col];
                if (mat == 3) {
                    if (r0 < Nn)
                        *(float2*)&out[(size_t)r0 * 128 + col] =
                            make_float2(acc[mi][nb][0] + bi.x, acc[mi][nb][1] + bi.y);
                    if (r0 + 8 < Nn)
                        *(float2*)&out[(size_t)(r0 + 8) * 128 + col] =
                            make_float2(acc[mi][nb][2] + bi.x, acc[mi][nb][3] + bi.y);
                } else {
                    __half* dst = (mat == 0) ? g_qh : (mat == 1) ? g_kh : g_vh;
                    if (r0 < Nn)
                        *(__half2*)&dst[(size_t)r0 * 128 + col] =
                            __floats2half2_rn(acc[mi][nb][0] + bi.x, acc[mi][nb][1] + bi.y);
                    if (r0 + 8 < Nn)
                        *(__half2*)&dst[(size_t)(r0 + 8) * 128 + col] =
                            __floats2half2_rn(acc[mi][nb][2] + bi.x, acc[mi][nb][3] + bi.y);
                }
            }
        }
    }
}

// ---------------- edge GEMM: e = msg @ We_bot + table(rel_t); alpha, vj ----------------
#define E_B_OFF   34816
#define E_SRC     69632
#define E_DST     70144
#define E_RLT     70656
#define EDGE_SMEM 71168
#define E_TILES   (Ee / 128)

__global__ void __launch_bounds__(256, 2) k_edge_mma(
    const int*   __restrict__ ei,
    const float* __restrict__ last_update,
    const float* __restrict__ t,
    const float* __restrict__ msg)
{
    extern __shared__ char sm[];
    uint32_t sbase = smem_u32(sm);
    int tid = threadIdx.x, w = tid >> 5, l = tid & 31;

    int*   sSrc = (int*)(sm + E_SRC);
    int*   sDst = (int*)(sm + E_DST);
    float* sRlt = (float*)(sm + E_RLT);

    for (int c = tid; c < 2048; c += 256) {
        int row = c >> 4, kc = c & 15;
        *(uint4*)(sm + E_B_OFF + row * 272 + kc * 16) = ((const uint4*)g_Webh)[c];
    }

    int rg = w >> 1, cg = w & 1;
    for (int tile = blockIdx.x; tile < E_TILES; tile += gridDim.x) {
        __syncthreads();           // previous epilogue done before overwriting meta/A
        if (tid < 128) {
            int e = tile * 128 + tid;
            int s = ei[e];
            sSrc[tid] = s;
            sDst[tid] = ei[Ee + e];
            sRlt[tid] = last_update[s] - t[e];
        }
        for (int c = tid; c < 2048; c += 256) {
            int row = c >> 4, kc = c & 15;
            const float4* mp = (const float4*)(msg + (size_t)(tile * 128 + row) * 128 + kc * 8);
            float4 m0 = mp[0], m1 = mp[1];
            __half2 h[4];
            h[0] = __floats2half2_rn(m0.x, m0.y); h[1] = __floats2half2_rn(m0.z, m0.w);
            h[2] = __floats2half2_rn(m1.x, m1.y); h[3] = __floats2half2_rn(m1.z, m1.w);
            *(uint4*)(sm + row * 272 + kc * 16) = *(uint4*)h;
        }
        __syncthreads();

        float acc[2][8][4];
#pragma unroll
        for (int mi = 0; mi < 2; mi++)
#pragma unroll
            for (int nb = 0; nb < 8; nb++)
#pragma unroll
                for (int j = 0; j < 4; j++) acc[mi][nb][j] = 0.0f;

#pragma unroll
        for (int ks = 0; ks < 8; ks++) {
            uint32_t af[2][4];
#pragma unroll
            for (int mi = 0; mi < 2; mi++) {
                uint32_t addr = sbase + (uint32_t)(rg * 32 + mi * 16 + (l & 15)) * 272
                              + ks * 32 + (l >> 4) * 16;
                ldsm_x4(af[mi], addr);
            }
            uint32_t bf[8][2];
#pragma unroll
            for (int nbp = 0; nbp < 4; nbp++) {
                uint32_t r[4];
                int n = cg * 64 + nbp * 16 + (l & 7) + ((l >> 4) << 3);
                uint32_t addr = sbase + E_B_OFF + (uint32_t)n * 272
                              + ks * 32 + ((l >> 3) & 1) * 16;
                ldsm_x4(r, addr);
                bf[nbp * 2][0] = r[0]; bf[nbp * 2][1] = r[1];
                bf[nbp * 2 + 1][0] = r[2]; bf[nbp * 2 + 1][1] = r[3];
            }
#pragma unroll
            for (int mi = 0; mi < 2; mi++)
#pragma unroll
                for (int nb = 0; nb < 8; nb++)
                    mma16816(acc[mi][nb], af[mi], bf[nb]);
        }
        __syncthreads();           // all A reads done; stage C (fp16) over A

#pragma unroll
        for (int mi = 0; mi < 2; mi++) {
            int r0 = rg * 32 + mi * 16 + (l >> 2);
#pragma unroll
            for (int nb = 0; nb < 8; nb++) {
                int col = cg * 64 + nb * 8 + 2 * (l & 3);
                *(__half2*)(sm + r0 * 272 + col * 2) =
                    __floats2half2_rn(acc[mi][nb][0], acc[mi][nb][1]);
                *(__half2*)(sm + (r0 + 8) * 272 + col * 2) =
                    __floats2half2_rn(acc[mi][nb][2], acc[mi][nb][3]);
            }
        }
        __syncthreads();

        // epilogue: thread -> (edge el, 64-col half hf)
        {
            int sp = w & 3, hf = w >> 2;
            int el = sp * 32 + l;
            int e = tile * 128 + el;
            int s = sSrc[el], d = sDst[el];

            float f = (sRlt[el] - TH0) * TSCALE;
            int i0 = (int)f;
            i0 = max(0, min(i0, TABN - 2));
            float fr = f - (float)i0;

            const uint4* t0p = (const uint4*)(g_tab + (size_t)i0 * 128 + hf * 64);
            const uint4* t1p = (const uint4*)(g_tab + (size_t)(i0 + 1) * 128 + hf * 64);
            const uint4* cp  = (const uint4*)(sm + el * 272 + hf * 128);
            const uint4* qp = (const uint4*)(g_qh + (size_t)d * 128 + hf * 64);
            const uint4* kp = (const uint4*)(g_kh + (size_t)s * 128 + hf * 64);
            const uint4* vp = (const uint4*)(g_vh + (size_t)s * 128 + hf * 64);
            uint4* op = (uint4*)(g_vj + (size_t)e * 128 + hf * 64);

            float dot = 0.0f;
#pragma unroll
            for (int i = 0; i < 8; i++) {
                uint4 qu = qp[i], ku = kp[i], vu = vp[i];
                uint4 cu = cp[i], g0u = t0p[i], g1u = t1p[i];
                __half2* q2 = (__half2*)&qu;
                __half2* k2 = (__half2*)&ku;
                __half2* v2 = (__half2*)&vu;
                __half2* c2 = (__half2*)&cu;
                __half2* g02 = (__half2*)&g0u;
                __half2* g12 = (__half2*)&g1u;
                __half2 o2[4];
#pragma unroll
                for (int j = 0; j < 4; j++) {
                    float2 cf = __half22float2(c2[j]);
                    float2 ga = __half22float2(g02[j]);
                    float2 gb = __half22float2(g12[j]);
                    float ea = cf.x + ga.x + fr * (gb.x - ga.x);
                    float eb = cf.y + ga.y + fr * (gb.y - ga.y);
                    float2 qf = __half22float2(q2[j]);
                    float2 kf = __half22float2(k2[j]);
                    float2 vf = __half22float2(v2[j]);
                    dot = fmaf(qf.x, kf.x + ea, dot);
                    dot = fmaf(qf.y, kf.y + eb, dot);
                    o2[j] = __floats2half2_rn(vf.x + ea, vf.y + eb);
                }
                op[i] = *(uint4*)o2;
            }
            float alpha = dot * 0.125f;
            g_alpha[e * 2 + hf] = alpha;
            atomicMaxF(&g_amax[d * 2 + hf], alpha);
        }
    }
}

// ---------------- exp + denominator ----------------
__global__ void k_expsum(const int* __restrict__ ei) {
    int i = blockIdx.x * blockDim.x + threadIdx.x;
    if (i >= Ee * 2) return;
    int e = i >> 1, h = i & 1;
    int d = ei[Ee + e];
    float ex = expf(g_alpha[i] - g_amax[d * 2 + h]);
    g_alpha[i] = ex;
    atomicAdd(&g_denom[d * 2 + h], ex);
}

// ---------------- weighted aggregation (warp per edge) ----------------
__global__ void __launch_bounds__(256) k_agg(const int* __restrict__ ei,
                                             float* __restrict__ out)
{
    int gtid = blockIdx.x * blockDim.x + threadIdx.x;
    int e = gtid >> 5;
    if (e >= Ee) return;
    int lane = threadIdx.x & 31;

    int d = ei[Ee + e];
    float2 ex  = *(const float2*)&g_alpha[e * 2];
    float2 den = *(const float2*)&g_denom[d * 2];
    float wgt = (lane < 16) ? (ex.x / den.x) : (ex.y / den.y);

    int c = lane * 4;
    const __half2* vp = (const __half2*)(g_vj + (size_t)e * 128 + c);
    float2 a = __half22float2(vp[0]);
    float2 b = __half22float2(vp[1]);
    float4 r;
    r.x = wgt * a.x; r.y = wgt * a.y; r.z = wgt * b.x; r.w = wgt * b.y;

    float* p = &out[(size_t)d * 128 + c];
    asm volatile("red.global.add.v4.f32 [%0], {%1, %2, %3, %4};"
                 :: "l"(p), "f"(r.x), "f"(r.y), "f"(r.z), "f"(r.w)
                 : "memory");
}

// ---------------- launch ----------------
extern "C" void kernel_launch(void* const* d_in, const int* in_sizes, int n_in,
                              void* d_out, int out_size)
{
    const float* x           = (const float*)d_in[0];
    const float* last_update = (const float*)d_in[1];
    const int*   ei          = (const int*)  d_in[2];
    const float* t           = (const float*)d_in[3];
    const float* msg         = (const float*)d_in[4];
    const float* Wt          = (const float*)d_in[5];
    const float* bt          = (const float*)d_in[6];
    const float* Wq          = (const float*)d_in[7];
    const float* bq          = (const float*)d_in[8];
    const float* Wk          = (const float*)d_in[9];
    const float* bk          = (const float*)d_in[10];
    const float* Wv          = (const float*)d_in[11];
    const float* bv          = (const float*)d_in[12];
    const float* We          = (const float*)d_in[13];
    const float* Wskip       = (const float*)d_in[14];
    const float* bskip       = (const float*)d_in[15];
    float* out = (float*)d_out;

    cudaFuncSetAttribute(k_table,    cudaFuncAttributeMaxDynamicSharedMemorySize, TB_SMEM);
    cudaFuncSetAttribute(k_node_mma, cudaFuncAttributeMaxDynamicSharedMemorySize, NODE_SMEM);
    cudaFuncSetAttribute(k_edge_mma, cudaFuncAttributeMaxDynamicSharedMemorySize, EDGE_SMEM);

    k_prep<<<(Nn * Dd + 255) / 256, 256>>>(x, We, Wq, Wk, Wv, Wskip);

    k_table<<<296, 256, TB_SMEM>>>(Wt, bt);

    dim3 gn(74, 4);
    k_node_mma<<<gn, 256, NODE_SMEM>>>(bq, bk, bv, bskip, out);

    k_edge_mma<<<296, 256, EDGE_SMEM>>>(ei, last_update, t, msg);

    k_expsum<<<(Ee * 2 + 255) / 256, 256>>>(ei);

    k_agg<<<(Ee * 32 + 255) / 256, 256>>>(ei, out);
}

// round 7
// speedup vs baseline: 4.7228x; 1.5031x over previous
#include <cuda_runtime.h>
#include <cuda_fp16.h>
#include <cstdint>
#include <math.h>

#define Nn 50000
#define Ee 800000
#define Dd 128

#define TABN 65536
#define TH0  (-1000.0f)
#define HSTEP   (2000.0f / 65535.0f)
#define TSCALE  (65535.0f / 2000.0f)

// ---------------- scratch (static device globals; no allocation) ----------------
__device__ __half g_xh[(size_t)Nn * Dd];
__device__ __half g_qh[(size_t)Nn * Dd];
__device__ __half g_kh[(size_t)Nn * Dd];
__device__ __half g_vh[(size_t)Nn * Dd];
__device__ __half g_Weth[128 * 128];       // [n][k] fp16: We_top^T (time-enc rows)
__device__ __half g_Webh[128 * 128];       // [n][k] fp16: We_bot^T (msg rows)
__device__ __half g_Wallh[512 * 128];      // [j][k], j = {q|k|v|skip}*128+n
__device__ __half g_tab[(size_t)TABN * 128]; // g(theta) table, fp16 (16.8MB)
__device__ __half g_vj[(size_t)Ee * Dd];   // v[src]+e, fp16 (205MB)
__device__ float  g_alpha[Ee * 2];
__device__ float  g_amax[Nn * 2];
__device__ float  g_denom[Nn * 2];

__device__ __forceinline__ void atomicMaxF(float* addr, float v) {
    if (v >= 0.0f) atomicMax((int*)addr, __float_as_int(v));
    else           atomicMin((unsigned int*)addr, __float_as_uint(v));
}

__device__ __forceinline__ uint32_t smem_u32(const void* p) {
    uint32_t a;
    asm("{ .reg .u64 t; cvta.to.shared.u64 t, %1; cvt.u32.u64 %0, t; }" : "=r"(a) : "l"(p));
    return a;
}

__device__ __forceinline__ void ldsm_x4(uint32_t* r, uint32_t addr) {
    asm volatile("ldmatrix.sync.aligned.m8n8.x4.shared.b16 {%0,%1,%2,%3}, [%4];"
                 : "=r"(r[0]), "=r"(r[1]), "=r"(r[2]), "=r"(r[3]) : "r"(addr));
}

__device__ __forceinline__ void mma16816(float* c, const uint32_t* a, const uint32_t* b) {
    asm volatile("mma.sync.aligned.m16n8k16.row.col.f32.f16.f16.f32 "
                 "{%0,%1,%2,%3}, {%4,%5,%6,%7}, {%8,%9}, {%0,%1,%2,%3};"
                 : "+f"(c[0]), "+f"(c[1]), "+f"(c[2]), "+f"(c[3])
                 : "r"(a[0]), "r"(a[1]), "r"(a[2]), "r"(a[3]), "r"(b[0]), "r"(b[1]));
}

// ---------------- prep: fp16 conversions + softmax init ----------------
__global__ void k_prep(const float* __restrict__ x, const float* __restrict__ We,
                       const float* __restrict__ Wq, const float* __restrict__ Wk,
                       const float* __restrict__ Wv, const float* __restrict__ Ws)
{
    int i = blockIdx.x * blockDim.x + threadIdx.x;
    if (i < Nn * Dd) g_xh[i] = __float2half_rn(x[i]);
    if (i < 128 * 128) {                 // transposed We halves
        int n = i >> 7, k = i & 127;
        g_Weth[i] = __float2half_rn(We[k * 128 + n]);
        g_Webh[i] = __float2half_rn(We[(k + 128) * 128 + n]);
    }
    if (i < 512 * 128) {                 // g_Wallh[j][kk] = Wm[kk][n]
        int j = i >> 7, kk = i & 127;
        int m = j >> 7, n = j & 127;
        const float* W = (m == 0) ? Wq : (m == 1) ? Wk : (m == 2) ? Wv : Ws;
        g_Wallh[i] = __float2half_rn(W[kk * 128 + n]);
    }
    if (i < Nn * 2) { g_amax[i] = -INFINITY; g_denom[i] = 0.0f; }
}

// ---------------- table build: g_tab[i][:] = cos(theta_i*Wt+bt) @ We_top ----------------
#define TB_B_OFF 34816
#define TB_WT    69632
#define TB_BT    70144
#define TB_SMEM  70656
#define TB_TILES (TABN / 128)

__global__ void __launch_bounds__(256, 2) k_table(const float* __restrict__ Wt,
                                                  const float* __restrict__ bt)
{
    extern __shared__ char sm[];
    uint32_t sbase = smem_u32(sm);
    int tid = threadIdx.x, w = tid >> 5, l = tid & 31;
    float* sWt = (float*)(sm + TB_WT);
    float* sBt = (float*)(sm + TB_BT);

    if (tid < 128) { sWt[tid] = Wt[tid]; sBt[tid] = bt[tid]; }
    for (int c = tid; c < 2048; c += 256) {
        int row = c >> 4, kc = c & 15;
        *(uint4*)(sm + TB_B_OFF + row * 272 + kc * 16) = ((const uint4*)g_Weth)[c];
    }

    int rg = w >> 1, cg = w & 1;
    for (int tile = blockIdx.x; tile < TB_TILES; tile += gridDim.x) {
        __syncthreads();
        for (int idx = tid; idx < 8192; idx += 256) {
            int row = idx >> 6, k2 = (idx & 63) * 2;
            float th = TH0 + (float)(tile * 128 + row) * HSTEP;
            float a0 = cosf(fmaf(th, sWt[k2],     sBt[k2]));
            float a1 = cosf(fmaf(th, sWt[k2 + 1], sBt[k2 + 1]));
            *(__half2*)(sm + row * 272 + k2 * 2) = __floats2half2_rn(a0, a1);
        }
        __syncthreads();

        float acc[2][8][4];
#pragma unroll
        for (int mi = 0; mi < 2; mi++)
#pragma unroll
            for (int nb = 0; nb < 8; nb++)
#pragma unroll
                for (int j = 0; j < 4; j++) acc[mi][nb][j] = 0.0f;

#pragma unroll
        for (int ks = 0; ks < 8; ks++) {
            uint32_t af[2][4];
#pragma unroll
            for (int mi = 0; mi < 2; mi++) {
                uint32_t addr = sbase + (uint32_t)(rg * 32 + mi * 16 + (l & 15)) * 272
                              + ks * 32 + (l >> 4) * 16;
                ldsm_x4(af[mi], addr);
            }
            uint32_t bf[8][2];
#pragma unroll
            for (int nbp = 0; nbp < 4; nbp++) {
                uint32_t r[4];
                int n = cg * 64 + nbp * 16 + (l & 7) + ((l >> 4) << 3);
                uint32_t addr = sbase + TB_B_OFF + (uint32_t)n * 272
                              + ks * 32 + ((l >> 3) & 1) * 16;
                ldsm_x4(r, addr);
                bf[nbp * 2][0] = r[0]; bf[nbp * 2][1] = r[1];
                bf[nbp * 2 + 1][0] = r[2]; bf[nbp * 2 + 1][1] = r[3];
            }
#pragma unroll
            for (int mi = 0; mi < 2; mi++)
#pragma unroll
                for (int nb = 0; nb < 8; nb++)
                    mma16816(acc[mi][nb], af[mi], bf[nb]);
        }

#pragma unroll
        for (int mi = 0; mi < 2; mi++) {
            int r0 = tile * 128 + rg * 32 + mi * 16 + (l >> 2);
#pragma unroll
            for (int nb = 0; nb < 8; nb++) {
                int col = cg * 64 + nb * 8 + 2 * (l & 3);
                *(__half2*)&g_tab[(size_t)r0 * 128 + col] =
                    __floats2half2_rn(acc[mi][nb][0], acc[mi][nb][1]);
                *(__half2*)&g_tab[(size_t)(r0 + 8) * 128 + col] =
                    __floats2half2_rn(acc[mi][nb][2], acc[mi][nb][3]);
            }
        }
    }
}

// ---------------- node GEMM: blockIdx.y selects matrix; B = one 128x128 weight ----------------
#define NODE_B_OFF 34816
#define NODE_SMEM  69632
#define N_TILES    391

__global__ void __launch_bounds__(256, 2) k_node_mma(
    const float* __restrict__ bq, const float* __restrict__ bk,
    const float* __restrict__ bv, const float* __restrict__ bs,
    float* __restrict__ out)
{
    extern __shared__ char sm[];
    uint32_t sbase = smem_u32(sm);
    int tid = threadIdx.x, w = tid >> 5, l = tid & 31;
    int mat = blockIdx.y;

    const __half* Wsrc = g_Wallh + (size_t)mat * 128 * 128;
    for (int c = tid; c < 2048; c += 256) {
        int row = c >> 4, kc = c & 15;
        *(uint4*)(sm + NODE_B_OFF + row * 272 + kc * 16) = ((const uint4*)Wsrc)[c];
    }

    int rg = w >> 1, cg = w & 1;
    for (int tile = blockIdx.x; tile < N_TILES; tile += gridDim.x) {
        int n0 = tile * 128;
        __syncthreads();
        for (int c = tid; c < 2048; c += 256) {
            int row = c >> 4, kc = c & 15;
            int nr = n0 + row;
            uint4 v = make_uint4(0, 0, 0, 0);
            if (nr < Nn) v = ((const uint4*)g_xh)[((size_t)nr * 128) / 8 + kc];
            *(uint4*)(sm + row * 272 + kc * 16) = v;
        }
        __syncthreads();

        float acc[2][8][4];
#pragma unroll
        for (int mi = 0; mi < 2; mi++)
#pragma unroll
            for (int nb = 0; nb < 8; nb++)
#pragma unroll
                for (int j = 0; j < 4; j++) acc[mi][nb][j] = 0.0f;

#pragma unroll
        for (int ks = 0; ks < 8; ks++) {
            uint32_t af[2][4];
#pragma unroll
            for (int mi = 0; mi < 2; mi++) {
                uint32_t addr = sbase + (uint32_t)(rg * 32 + mi * 16 + (l & 15)) * 272
                              + ks * 32 + (l >> 4) * 16;
                ldsm_x4(af[mi], addr);
            }
            uint32_t bf[8][2];
#pragma unroll
            for (int nbp = 0; nbp < 4; nbp++) {
                uint32_t r[4];
                int n = cg * 64 + nbp * 16 + (l & 7) + ((l >> 4) << 3);
                uint32_t addr = sbase + NODE_B_OFF + (uint32_t)n * 272
                              + ks * 32 + ((l >> 3) & 1) * 16;
                ldsm_x4(r, addr);
                bf[nbp * 2][0] = r[0]; bf[nbp * 2][1] = r[1];
                bf[nbp * 2 + 1][0] = r[2]; bf[nbp * 2 + 1][1] = r[3];
            }
#pragma unroll
            for (int mi = 0; mi < 2; mi++)
#pragma unroll
                for (int nb = 0; nb < 8; nb++)
                    mma16816(acc[mi][nb], af[mi], bf[nb]);
        }

        const float* bias = (mat == 0) ? bq : (mat == 1) ? bk : (mat == 2) ? bv : bs;
#pragma unroll
        for (int mi = 0; mi < 2; mi++) {
            int r0 = n0 + rg * 32 + mi * 16 + (l >> 2);
#pragma unroll
            for (int nb = 0; nb < 8; nb++) {
                int col = cg * 64 + nb * 8 + 2 * (l & 3);
                float2 bi = *(const float2*)&bias[col];
                if (mat == 3) {
                    if (r0 < Nn)
                        *(float2*)&out[(size_t)r0 * 128 + col] =
                            make_float2(acc[mi][nb][0] + bi.x, acc[mi][nb][1] + bi.y);
                    if (r0 + 8 < Nn)
                        *(float2*)&out[(size_t)(r0 + 8) * 128 + col] =
                            make_float2(acc[mi][nb][2] + bi.x, acc[mi][nb][3] + bi.y);
                } else {
                    __half* dst = (mat == 0) ? g_qh : (mat == 1) ? g_kh : g_vh;
                    if (r0 < Nn)
                        *(__half2*)&dst[(size_t)r0 * 128 + col] =
                            __floats2half2_rn(acc[mi][nb][0] + bi.x, acc[mi][nb][1] + bi.y);
                    if (r0 + 8 < Nn)
                        *(__half2*)&dst[(size_t)(r0 + 8) * 128 + col] =
                            __floats2half2_rn(acc[mi][nb][2] + bi.x, acc[mi][nb][3] + bi.y);
                }
            }
        }
    }
}

// ---------------- edge GEMM: e = msg @ We_bot + table(rel_t); alpha, vj ----------------
#define E_B_OFF   34816
#define E_SRC     69632
#define E_DST     70144
#define E_RLT     70656
#define EDGE_SMEM 71168
#define E_TILES   (Ee / 128)

__global__ void __launch_bounds__(256, 2) k_edge_mma(
    const int*   __restrict__ ei,
    const float* __restrict__ last_update,
    const float* __restrict__ t,
    const float* __restrict__ msg)
{
    extern __shared__ char sm[];
    uint32_t sbase = smem_u32(sm);
    int tid = threadIdx.x, w = tid >> 5, l = tid & 31;

    int*   sSrc = (int*)(sm + E_SRC);
    int*   sDst = (int*)(sm + E_DST);
    float* sRlt = (float*)(sm + E_RLT);

    for (int c = tid; c < 2048; c += 256) {
        int row = c >> 4, kc = c & 15;
        *(uint4*)(sm + E_B_OFF + row * 272 + kc * 16) = ((const uint4*)g_Webh)[c];
    }

    int rg = w >> 1, cg = w & 1;
    for (int tile = blockIdx.x; tile < E_TILES; tile += gridDim.x) {
        __syncthreads();           // previous epilogue done before overwriting meta/A
        if (tid < 128) {
            int e = tile * 128 + tid;
            int s = ei[e];
            sSrc[tid] = s;
            sDst[tid] = ei[Ee + e];
            sRlt[tid] = last_update[s] - t[e];
        }
        for (int c = tid; c < 2048; c += 256) {
            int row = c >> 4, kc = c & 15;
            const float4* mp = (const float4*)(msg + (size_t)(tile * 128 + row) * 128 + kc * 8);
            float4 m0 = mp[0], m1 = mp[1];
            __half2 h[4];
            h[0] = __floats2half2_rn(m0.x, m0.y); h[1] = __floats2half2_rn(m0.z, m0.w);
            h[2] = __floats2half2_rn(m1.x, m1.y); h[3] = __floats2half2_rn(m1.z, m1.w);
            *(uint4*)(sm + row * 272 + kc * 16) = *(uint4*)h;
        }
        __syncthreads();

        float acc[2][8][4];
#pragma unroll
        for (int mi = 0; mi < 2; mi++)
#pragma unroll
            for (int nb = 0; nb < 8; nb++)
#pragma unroll
                for (int j = 0; j < 4; j++) acc[mi][nb][j] = 0.0f;

#pragma unroll
        for (int ks = 0; ks < 8; ks++) {
            uint32_t af[2][4];
#pragma unroll
            for (int mi = 0; mi < 2; mi++) {
                uint32_t addr = sbase + (uint32_t)(rg * 32 + mi * 16 + (l & 15)) * 272
                              + ks * 32 + (l >> 4) * 16;
                ldsm_x4(af[mi], addr);
            }
            uint32_t bf[8][2];
#pragma unroll
            for (int nbp = 0; nbp < 4; nbp++) {
                uint32_t r[4];
                int n = cg * 64 + nbp * 16 + (l & 7) + ((l >> 4) << 3);
                uint32_t addr = sbase + E_B_OFF + (uint32_t)n * 272
                              + ks * 32 + ((l >> 3) & 1) * 16;
                ldsm_x4(r, addr);
                bf[nbp * 2][0] = r[0]; bf[nbp * 2][1] = r[1];
                bf[nbp * 2 + 1][0] = r[2]; bf[nbp * 2 + 1][1] = r[3];
            }
#pragma unroll
            for (int mi = 0; mi < 2; mi++)
#pragma unroll
                for (int nb = 0; nb < 8; nb++)
                    mma16816(acc[mi][nb], af[mi], bf[nb]);
        }
        __syncthreads();           // all A reads done; stage C (fp16) over A

#pragma unroll
        for (int mi = 0; mi < 2; mi++) {
            int r0 = rg * 32 + mi * 16 + (l >> 2);
#pragma unroll
            for (int nb = 0; nb < 8; nb++) {
                int col = cg * 64 + nb * 8 + 2 * (l & 3);
                *(__half2*)(sm + r0 * 272 + col * 2) =
                    __floats2half2_rn(acc[mi][nb][0], acc[mi][nb][1]);
                *(__half2*)(sm + (r0 + 8) * 272 + col * 2) =
                    __floats2half2_rn(acc[mi][nb][2], acc[mi][nb][3]);
            }
        }
        __syncthreads();

        // epilogue: 8 lanes per (edge, half) task; warp iteration = 4 tasks = 2 full edges.
        // Coalesced: each warp LDG.128 touches 2 random rows x 256B contiguous.
        {
            int group = l >> 3, sub = l & 7;
#pragma unroll
            for (int it = 0; it < 8; it++) {
                int T = w * 32 + it * 4 + group;   // 0..255
                int el = T >> 1, hf = T & 1;
                int e = tile * 128 + el;
                int s = sSrc[el], d = sDst[el];

                float f = (sRlt[el] - TH0) * TSCALE;
                int i0 = (int)f;
                i0 = max(0, min(i0, TABN - 2));
                float fr = f - (float)i0;

                int cb = hf * 64 + sub * 8;        // column base (halfs)

                uint4 cu  = *(const uint4*)(sm + el * 272 + cb * 2);
                uint4 qu  = *(const uint4*)(g_qh + (size_t)d * 128 + cb);
                uint4 ku  = *(const uint4*)(g_kh + (size_t)s * 128 + cb);
                uint4 vu  = *(const uint4*)(g_vh + (size_t)s * 128 + cb);
                uint4 g0u = *(const uint4*)(g_tab + (size_t)i0 * 128 + cb);
                uint4 g1u = *(const uint4*)(g_tab + (size_t)(i0 + 1) * 128 + cb);

                __half2* q2  = (__half2*)&qu;
                __half2* k2  = (__half2*)&ku;
                __half2* v2  = (__half2*)&vu;
                __half2* c2  = (__half2*)&cu;
                __half2* g02 = (__half2*)&g0u;
                __half2* g12 = (__half2*)&g1u;

                float dot = 0.0f;
                __half2 o2[4];
#pragma unroll
                for (int j = 0; j < 4; j++) {
                    float2 cf = __half22float2(c2[j]);
                    float2 ga = __half22float2(g02[j]);
                    float2 gb = __half22float2(g12[j]);
                    float ea = cf.x + ga.x + fr * (gb.x - ga.x);
                    float eb = cf.y + ga.y + fr * (gb.y - ga.y);
                    float2 qf = __half22float2(q2[j]);
                    float2 kf = __half22float2(k2[j]);
                    float2 vf = __half22float2(v2[j]);
                    dot = fmaf(qf.x, kf.x + ea, dot);
                    dot = fmaf(qf.y, kf.y + eb, dot);
                    o2[j] = __floats2half2_rn(vf.x + ea, vf.y + eb);
                }
                *(uint4*)(g_vj + (size_t)e * 128 + cb) = *(uint4*)o2;

                dot += __shfl_xor_sync(0xffffffffu, dot, 1);
                dot += __shfl_xor_sync(0xffffffffu, dot, 2);
                dot += __shfl_xor_sync(0xffffffffu, dot, 4);
                if (sub == 0) {
                    float alpha = dot * 0.125f;
                    g_alpha[e * 2 + hf] = alpha;
                    atomicMaxF(&g_amax[d * 2 + hf], alpha);
                }
            }
        }
    }
}

// ---------------- exp + denominator ----------------
__global__ void k_expsum(const int* __restrict__ ei) {
    int i = blockIdx.x * blockDim.x + threadIdx.x;
    if (i >= Ee * 2) return;
    int e = i >> 1, h = i & 1;
    int d = ei[Ee + e];
    float ex = expf(g_alpha[i] - g_amax[d * 2 + h]);
    g_alpha[i] = ex;
    atomicAdd(&g_denom[d * 2 + h], ex);
}

// ---------------- weighted aggregation (warp per edge) ----------------
__global__ void __launch_bounds__(256) k_agg(const int* __restrict__ ei,
                                             float* __restrict__ out)
{
    int gtid = blockIdx.x * blockDim.x + threadIdx.x;
    int e = gtid >> 5;
    if (e >= Ee) return;
    int lane = threadIdx.x & 31;

    int d = ei[Ee + e];
    float2 ex  = *(const float2*)&g_alpha[e * 2];
    float2 den = *(const float2*)&g_denom[d * 2];
    float wgt = (lane < 16) ? (ex.x / den.x) : (ex.y / den.y);

    int c = lane * 4;
    const __half2* vp = (const __half2*)(g_vj + (size_t)e * 128 + c);
    float2 a = __half22float2(vp[0]);
    float2 b = __half22float2(vp[1]);
    float4 r;
    r.x = wgt * a.x; r.y = wgt * a.y; r.z = wgt * b.x; r.w = wgt * b.y;

    float* p = &out[(size_t)d * 128 + c];
    asm volatile("red.global.add.v4.f32 [%0], {%1, %2, %3, %4};"
                 :: "l"(p), "f"(r.x), "f"(r.y), "f"(r.z), "f"(r.w)
                 : "memory");
}

// ---------------- launch ----------------
extern "C" void kernel_launch(void* const* d_in, const int* in_sizes, int n_in,
                              void* d_out, int out_size)
{
    const float* x           = (const float*)d_in[0];
    const float* last_update = (const float*)d_in[1];
    const int*   ei          = (const int*)  d_in[2];
    const float* t           = (const float*)d_in[3];
    const float* msg         = (const float*)d_in[4];
    const float* Wt          = (const float*)d_in[5];
    const float* bt          = (const float*)d_in[6];
    const float* Wq          = (const float*)d_in[7];
    const float* bq          = (const float*)d_in[8];
    const float* Wk          = (const float*)d_in[9];
    const float* bk          = (const float*)d_in[10];
    const float* Wv          = (const float*)d_in[11];
    const float* bv          = (const float*)d_in[12];
    const float* We          = (const float*)d_in[13];
    const float* Wskip       = (const float*)d_in[14];
    const float* bskip       = (const float*)d_in[15];
    float* out = (float*)d_out;

    cudaFuncSetAttribute(k_table,    cudaFuncAttributeMaxDynamicSharedMemorySize, TB_SMEM);
    cudaFuncSetAttribute(k_node_mma, cudaFuncAttributeMaxDynamicSharedMemorySize, NODE_SMEM);
    cudaFuncSetAttribute(k_edge_mma, cudaFuncAttributeMaxDynamicSharedMemorySize, EDGE_SMEM);

    k_prep<<<(Nn * Dd + 255) / 256, 256>>>(x, We, Wq, Wk, Wv, Wskip);

    k_table<<<296, 256, TB_SMEM>>>(Wt, bt);

    dim3 gn(74, 4);
    k_node_mma<<<gn, 256, NODE_SMEM>>>(bq, bk, bv, bskip, out);

    k_edge_mma<<<296, 256, EDGE_SMEM>>>(ei, last_update, t, msg);

    k_expsum<<<(Ee * 2 + 255) / 256, 256>>>(ei);

    k_agg<<<(Ee * 32 + 255) / 256, 256>>>(ei, out);
}

// round 8
// speedup vs baseline: 5.2927x; 1.1207x over previous
#include <cuda_runtime.h>
#include <cuda_fp16.h>
#include <cstdint>
#include <math.h>

#define Nn 50000
#define Ee 800000
#define Dd 128

#define TABN 65536
#define TH0  (-1000.0f)
#define HSTEP   (2000.0f / 65535.0f)
#define TSCALE  (65535.0f / 2000.0f)

// ---------------- scratch (static device globals; no allocation) ----------------
__device__ __half g_xh[(size_t)Nn * Dd];
__device__ __half g_qh[(size_t)Nn * Dd];
__device__ __half g_kh[(size_t)Nn * Dd];
__device__ __half g_vh[(size_t)Nn * Dd];
__device__ __half g_Weth[128 * 128];       // [n][k] fp16: We_top^T
__device__ __half g_Webh[128 * 128];       // [n][k] fp16: We_bot^T
__device__ __half g_Wallh[512 * 128];      // [j][k], j = {q|k|v|skip}*128+n
__device__ __half g_tab[(size_t)TABN * 128]; // g(theta) table, fp16 (16.8MB)
__device__ __half g_vj[(size_t)Ee * Dd];   // v[src]+e, fp16 (205MB)
__device__ float  g_alpha[Ee * 2];
__device__ float  g_amax[Nn * 2];
__device__ float  g_denom[Nn * 2];

__device__ __forceinline__ void atomicMaxF(float* addr, float v) {
    if (v >= 0.0f) atomicMax((int*)addr, __float_as_int(v));
    else           atomicMin((unsigned int*)addr, __float_as_uint(v));
}

__device__ __forceinline__ uint32_t smem_u32(const void* p) {
    uint32_t a;
    asm("{ .reg .u64 t; cvta.to.shared.u64 t, %1; cvt.u32.u64 %0, t; }" : "=r"(a) : "l"(p));
    return a;
}

__device__ __forceinline__ void ldsm_x4(uint32_t* r, uint32_t addr) {
    asm volatile("ldmatrix.sync.aligned.m8n8.x4.shared.b16 {%0,%1,%2,%3}, [%4];"
                 : "=r"(r[0]), "=r"(r[1]), "=r"(r[2]), "=r"(r[3]) : "r"(addr));
}

__device__ __forceinline__ void mma16816(float* c, const uint32_t* a, const uint32_t* b) {
    asm volatile("mma.sync.aligned.m16n8k16.row.col.f32.f16.f16.f32 "
                 "{%0,%1,%2,%3}, {%4,%5,%6,%7}, {%8,%9}, {%0,%1,%2,%3};"
                 : "+f"(c[0]), "+f"(c[1]), "+f"(c[2]), "+f"(c[3])
                 : "r"(a[0]), "r"(a[1]), "r"(a[2]), "r"(a[3]), "r"(b[0]), "r"(b[1]));
}

// ---------------- prep ----------------
__global__ void k_prep(const float* __restrict__ x, const float* __restrict__ We,
                       const float* __restrict__ Wq, const float* __restrict__ Wk,
                       const float* __restrict__ Wv, const float* __restrict__ Ws)
{
    int i = blockIdx.x * blockDim.x + threadIdx.x;
    if (i < Nn * Dd) g_xh[i] = __float2half_rn(x[i]);
    if (i < 128 * 128) {
        int n = i >> 7, k = i & 127;
        g_Weth[i] = __float2half_rn(We[k * 128 + n]);
        g_Webh[i] = __float2half_rn(We[(k + 128) * 128 + n]);
    }
    if (i < 512 * 128) {
        int j = i >> 7, kk = i & 127;
        int m = j >> 7, n = j & 127;
        const float* W = (m == 0) ? Wq : (m == 1) ? Wk : (m == 2) ? Wv : Ws;
        g_Wallh[i] = __float2half_rn(W[kk * 128 + n]);
    }
    if (i < Nn * 2) { g_amax[i] = -INFINITY; g_denom[i] = 0.0f; }
}

// ---------------- table build ----------------
#define TB_B_OFF 34816
#define TB_WT    69632
#define TB_BT    70144
#define TB_SMEM  70656
#define TB_TILES (TABN / 128)

__global__ void __launch_bounds__(256, 2) k_table(const float* __restrict__ Wt,
                                                  const float* __restrict__ bt)
{
    extern __shared__ char sm[];
    uint32_t sbase = smem_u32(sm);
    int tid = threadIdx.x, w = tid >> 5, l = tid & 31;
    float* sWt = (float*)(sm + TB_WT);
    float* sBt = (float*)(sm + TB_BT);

    if (tid < 128) { sWt[tid] = Wt[tid]; sBt[tid] = bt[tid]; }
    for (int c = tid; c < 2048; c += 256) {
        int row = c >> 4, kc = c & 15;
        *(uint4*)(sm + TB_B_OFF + row * 272 + kc * 16) = ((const uint4*)g_Weth)[c];
    }

    int rg = w >> 1, cg = w & 1;
    for (int tile = blockIdx.x; tile < TB_TILES; tile += gridDim.x) {
        __syncthreads();
        for (int idx = tid; idx < 8192; idx += 256) {
            int row = idx >> 6, k2 = (idx & 63) * 2;
            float th = TH0 + (float)(tile * 128 + row) * HSTEP;
            float a0 = cosf(fmaf(th, sWt[k2],     sBt[k2]));
            float a1 = cosf(fmaf(th, sWt[k2 + 1], sBt[k2 + 1]));
            *(__half2*)(sm + row * 272 + k2 * 2) = __floats2half2_rn(a0, a1);
        }
        __syncthreads();

        float acc[2][8][4];
#pragma unroll
        for (int mi = 0; mi < 2; mi++)
#pragma unroll
            for (int nb = 0; nb < 8; nb++)
#pragma unroll
                for (int j = 0; j < 4; j++) acc[mi][nb][j] = 0.0f;

#pragma unroll
        for (int ks = 0; ks < 8; ks++) {
            uint32_t af[2][4];
#pragma unroll
            for (int mi = 0; mi < 2; mi++) {
                uint32_t addr = sbase + (uint32_t)(rg * 32 + mi * 16 + (l & 15)) * 272
                              + ks * 32 + (l >> 4) * 16;
                ldsm_x4(af[mi], addr);
            }
            uint32_t bf[8][2];
#pragma unroll
            for (int nbp = 0; nbp < 4; nbp++) {
                uint32_t r[4];
                int n = cg * 64 + nbp * 16 + (l & 7) + ((l >> 4) << 3);
                uint32_t addr = sbase + TB_B_OFF + (uint32_t)n * 272
                              + ks * 32 + ((l >> 3) & 1) * 16;
                ldsm_x4(r, addr);
                bf[nbp * 2][0] = r[0]; bf[nbp * 2][1] = r[1];
                bf[nbp * 2 + 1][0] = r[2]; bf[nbp * 2 + 1][1] = r[3];
            }
#pragma unroll
            for (int mi = 0; mi < 2; mi++)
#pragma unroll
                for (int nb = 0; nb < 8; nb++)
                    mma16816(acc[mi][nb], af[mi], bf[nb]);
        }

#pragma unroll
        for (int mi = 0; mi < 2; mi++) {
            int r0 = tile * 128 + rg * 32 + mi * 16 + (l >> 2);
#pragma unroll
            for (int nb = 0; nb < 8; nb++) {
                int col = cg * 64 + nb * 8 + 2 * (l & 3);
                *(__half2*)&g_tab[(size_t)r0 * 128 + col] =
                    __floats2half2_rn(acc[mi][nb][0], acc[mi][nb][1]);
                *(__half2*)&g_tab[(size_t)(r0 + 8) * 128 + col] =
                    __floats2half2_rn(acc[mi][nb][2], acc[mi][nb][3]);
            }
        }
    }
}

// ---------------- node GEMM ----------------
#define NODE_B_OFF 34816
#define NODE_SMEM  69632
#define N_TILES    391

__global__ void __launch_bounds__(256, 2) k_node_mma(
    const float* __restrict__ bq, const float* __restrict__ bk,
    const float* __restrict__ bv, const float* __restrict__ bs,
    float* __restrict__ out)
{
    extern __shared__ char sm[];
    uint32_t sbase = smem_u32(sm);
    int tid = threadIdx.x, w = tid >> 5, l = tid & 31;
    int mat = blockIdx.y;

    const __half* Wsrc = g_Wallh + (size_t)mat * 128 * 128;
    for (int c = tid; c < 2048; c += 256) {
        int row = c >> 4, kc = c & 15;
        *(uint4*)(sm + NODE_B_OFF + row * 272 + kc * 16) = ((const uint4*)Wsrc)[c];
    }

    int rg = w >> 1, cg = w & 1;
    for (int tile = blockIdx.x; tile < N_TILES; tile += gridDim.x) {
        int n0 = tile * 128;
        __syncthreads();
        for (int c = tid; c < 2048; c += 256) {
            int row = c >> 4, kc = c & 15;
            int nr = n0 + row;
            uint4 v = make_uint4(0, 0, 0, 0);
            if (nr < Nn) v = ((const uint4*)g_xh)[((size_t)nr * 128) / 8 + kc];
            *(uint4*)(sm + row * 272 + kc * 16) = v;
        }
        __syncthreads();

        float acc[2][8][4];
#pragma unroll
        for (int mi = 0; mi < 2; mi++)
#pragma unroll
            for (int nb = 0; nb < 8; nb++)
#pragma unroll
                for (int j = 0; j < 4; j++) acc[mi][nb][j] = 0.0f;

#pragma unroll
        for (int ks = 0; ks < 8; ks++) {
            uint32_t af[2][4];
#pragma unroll
            for (int mi = 0; mi < 2; mi++) {
                uint32_t addr = sbase + (uint32_t)(rg * 32 + mi * 16 + (l & 15)) * 272
                              + ks * 32 + (l >> 4) * 16;
                ldsm_x4(af[mi], addr);
            }
            uint32_t bf[8][2];
#pragma unroll
            for (int nbp = 0; nbp < 4; nbp++) {
                uint32_t r[4];
                int n = cg * 64 + nbp * 16 + (l & 7) + ((l >> 4) << 3);
                uint32_t addr = sbase + NODE_B_OFF + (uint32_t)n * 272
                              + ks * 32 + ((l >> 3) & 1) * 16;
                ldsm_x4(r, addr);
                bf[nbp * 2][0] = r[0]; bf[nbp * 2][1] = r[1];
                bf[nbp * 2 + 1][0] = r[2]; bf[nbp * 2 + 1][1] = r[3];
            }
#pragma unroll
            for (int mi = 0; mi < 2; mi++)
#pragma unroll
                for (int nb = 0; nb < 8; nb++)
                    mma16816(acc[mi][nb], af[mi], bf[nb]);
        }

        const float* bias = (mat == 0) ? bq : (mat == 1) ? bk : (mat == 2) ? bv : bs;
#pragma unroll
        for (int mi = 0; mi < 2; mi++) {
            int r0 = n0 + rg * 32 + mi * 16 + (l >> 2);
#pragma unroll
            for (int nb = 0; nb < 8; nb++) {
                int col = cg * 64 + nb * 8 + 2 * (l & 3);
                float2 bi = *(const float2*)&bias[col];
                if (mat == 3) {
                    if (r0 < Nn)
                        *(float2*)&out[(size_t)r0 * 128 + col] =
                            make_float2(acc[mi][nb][0] + bi.x, acc[mi][nb][1] + bi.y);
                    if (r0 + 8 < Nn)
                        *(float2*)&out[(size_t)(r0 + 8) * 128 + col] =
                            make_float2(acc[mi][nb][2] + bi.x, acc[mi][nb][3] + bi.y);
                } else {
                    __half* dst = (mat == 0) ? g_qh : (mat == 1) ? g_kh : g_vh;
                    if (r0 < Nn)
                        *(__half2*)&dst[(size_t)r0 * 128 + col] =
                            __floats2half2_rn(acc[mi][nb][0] + bi.x, acc[mi][nb][1] + bi.y);
                    if (r0 + 8 < Nn)
                        *(__half2*)&dst[(size_t)(r0 + 8) * 128 + col] =
                            __floats2half2_rn(acc[mi][nb][2] + bi.x, acc[mi][nb][3] + bi.y);
                }
            }
        }
    }
}

// ---------------- edge GEMM: 512 threads, warp tile 32x32 ----------------
#define E_B_OFF   34816
#define E_SRC     69632
#define E_DST     70144
#define E_RLT     70656
#define EDGE_SMEM 71168
#define E_TILES   (Ee / 128)

__global__ void __launch_bounds__(512, 2) k_edge_mma(
    const int*   __restrict__ ei,
    const float* __restrict__ last_update,
    const float* __restrict__ t,
    const float* __restrict__ msg)
{
    extern __shared__ char sm[];
    uint32_t sbase = smem_u32(sm);
    int tid = threadIdx.x, w = tid >> 5, l = tid & 31;

    int*   sSrc = (int*)(sm + E_SRC);
    int*   sDst = (int*)(sm + E_DST);
    float* sRlt = (float*)(sm + E_RLT);

    for (int c = tid; c < 2048; c += 512) {
        int row = c >> 4, kc = c & 15;
        *(uint4*)(sm + E_B_OFF + row * 272 + kc * 16) = ((const uint4*)g_Webh)[c];
    }

    int rg = w >> 2, cg = w & 3;   // warp tile: rows rg*32.., cols cg*32..
    for (int tile = blockIdx.x; tile < E_TILES; tile += gridDim.x) {
        __syncthreads();
        if (tid < 128) {
            int e = tile * 128 + tid;
            int s = ei[e];
            sSrc[tid] = s;
            sDst[tid] = ei[Ee + e];
            sRlt[tid] = last_update[s] - t[e];
        }
        for (int c = tid; c < 2048; c += 512) {
            int row = c >> 4, kc = c & 15;
            const float4* mp = (const float4*)(msg + (size_t)(tile * 128 + row) * 128 + kc * 8);
            float4 m0 = mp[0], m1 = mp[1];
            __half2 h[4];
            h[0] = __floats2half2_rn(m0.x, m0.y); h[1] = __floats2half2_rn(m0.z, m0.w);
            h[2] = __floats2half2_rn(m1.x, m1.y); h[3] = __floats2half2_rn(m1.z, m1.w);
            *(uint4*)(sm + row * 272 + kc * 16) = *(uint4*)h;
        }
        __syncthreads();

        float acc[2][4][4];
#pragma unroll
        for (int mi = 0; mi < 2; mi++)
#pragma unroll
            for (int nb = 0; nb < 4; nb++)
#pragma unroll
                for (int j = 0; j < 4; j++) acc[mi][nb][j] = 0.0f;

#pragma unroll
        for (int ks = 0; ks < 8; ks++) {
            uint32_t af[2][4];
#pragma unroll
            for (int mi = 0; mi < 2; mi++) {
                uint32_t addr = sbase + (uint32_t)(rg * 32 + mi * 16 + (l & 15)) * 272
                              + ks * 32 + (l >> 4) * 16;
                ldsm_x4(af[mi], addr);
            }
            uint32_t bf[4][2];
#pragma unroll
            for (int nbp = 0; nbp < 2; nbp++) {
                uint32_t r[4];
                int n = cg * 32 + nbp * 16 + (l & 7) + ((l >> 4) << 3);
                uint32_t addr = sbase + E_B_OFF + (uint32_t)n * 272
                              + ks * 32 + ((l >> 3) & 1) * 16;
                ldsm_x4(r, addr);
                bf[nbp * 2][0] = r[0]; bf[nbp * 2][1] = r[1];
                bf[nbp * 2 + 1][0] = r[2]; bf[nbp * 2 + 1][1] = r[3];
            }
#pragma unroll
            for (int mi = 0; mi < 2; mi++)
#pragma unroll
                for (int nb = 0; nb < 4; nb++)
                    mma16816(acc[mi][nb], af[mi], bf[nb]);
        }
        __syncthreads();           // all A reads done; stage C (fp16) over A

#pragma unroll
        for (int mi = 0; mi < 2; mi++) {
            int r0 = rg * 32 + mi * 16 + (l >> 2);
#pragma unroll
            for (int nb = 0; nb < 4; nb++) {
                int col = cg * 32 + nb * 8 + 2 * (l & 3);
                *(__half2*)(sm + r0 * 272 + col * 2) =
                    __floats2half2_rn(acc[mi][nb][0], acc[mi][nb][1]);
                *(__half2*)(sm + (r0 + 8) * 272 + col * 2) =
                    __floats2half2_rn(acc[mi][nb][2], acc[mi][nb][3]);
            }
        }
        __syncthreads();

        // epilogue: 8 lanes per (edge, half) task; 16 warps x 16 tasks
        {
            int group = l >> 3, sub = l & 7;
#pragma unroll
            for (int it = 0; it < 4; it++) {
                int T = w * 16 + it * 4 + group;   // 0..255
                int el = T >> 1, hf = T & 1;
                int e = tile * 128 + el;
                int s = sSrc[el], d = sDst[el];

                float f = (sRlt[el] - TH0) * TSCALE;
                int i0 = (int)f;
                i0 = max(0, min(i0, TABN - 2));
                float fr = f - (float)i0;

                int cb = hf * 64 + sub * 8;

                uint4 cu  = *(const uint4*)(sm + el * 272 + cb * 2);
                uint4 qu  = *(const uint4*)(g_qh + (size_t)d * 128 + cb);
                uint4 ku  = *(const uint4*)(g_kh + (size_t)s * 128 + cb);
                uint4 vu  = *(const uint4*)(g_vh + (size_t)s * 128 + cb);
                uint4 g0u = *(const uint4*)(g_tab + (size_t)i0 * 128 + cb);
                uint4 g1u = *(const uint4*)(g_tab + (size_t)(i0 + 1) * 128 + cb);

                __half2* q2  = (__half2*)&qu;
                __half2* k2  = (__half2*)&ku;
                __half2* v2  = (__half2*)&vu;
                __half2* c2  = (__half2*)&cu;
                __half2* g02 = (__half2*)&g0u;
                __half2* g12 = (__half2*)&g1u;

                float dot = 0.0f;
                __half2 o2[4];
#pragma unroll
                for (int j = 0; j < 4; j++) {
                    float2 cf = __half22float2(c2[j]);
                    float2 ga = __half22float2(g02[j]);
                    float2 gb = __half22float2(g12[j]);
                    float ea = cf.x + ga.x + fr * (gb.x - ga.x);
                    float eb = cf.y + ga.y + fr * (gb.y - ga.y);
                    float2 qf = __half22float2(q2[j]);
                    float2 kf = __half22float2(k2[j]);
                    float2 vf = __half22float2(v2[j]);
                    dot = fmaf(qf.x, kf.x + ea, dot);
                    dot = fmaf(qf.y, kf.y + eb, dot);
                    o2[j] = __floats2half2_rn(vf.x + ea, vf.y + eb);
                }
                *(uint4*)(g_vj + (size_t)e * 128 + cb) = *(uint4*)o2;

                dot += __shfl_xor_sync(0xffffffffu, dot, 1);
                dot += __shfl_xor_sync(0xffffffffu, dot, 2);
                dot += __shfl_xor_sync(0xffffffffu, dot, 4);
                if (sub == 0) {
                    float alpha = dot * 0.125f;
                    g_alpha[e * 2 + hf] = alpha;
                    atomicMaxF(&g_amax[d * 2 + hf], alpha);
                }
            }
        }
    }
}

// ---------------- exp + denominator ----------------
__global__ void k_expsum(const int* __restrict__ ei) {
    int i = blockIdx.x * blockDim.x + threadIdx.x;
    if (i >= Ee * 2) return;
    int e = i >> 1, h = i & 1;
    int d = ei[Ee + e];
    float ex = expf(g_alpha[i] - g_amax[d * 2 + h]);
    g_alpha[i] = ex;
    atomicAdd(&g_denom[d * 2 + h], ex);
}

// ---------------- weighted aggregation: 16 lanes/edge, ILP 4 ----------------
#define AGG_CHUNK (Ee / 4)   // 200000

__global__ void __launch_bounds__(256) k_agg(const int* __restrict__ ei,
                                             float* __restrict__ out)
{
    int tid = blockIdx.x * blockDim.x + threadIdx.x;
    int g = tid >> 4, sub = tid & 15;
    if (g >= AGG_CHUNK) return;

    int d[4];
    uint4 vju[4];
    float2 exv[4];
#pragma unroll
    for (int j = 0; j < 4; j++) {
        int e = g + j * AGG_CHUNK;
        d[j]   = ei[Ee + e];
        vju[j] = *(const uint4*)(g_vj + (size_t)e * 128 + sub * 8);
        exv[j] = *(const float2*)&g_alpha[e * 2];
    }
    float2 denv[4];
#pragma unroll
    for (int j = 0; j < 4; j++) denv[j] = *(const float2*)&g_denom[d[j] * 2];

#pragma unroll
    for (int j = 0; j < 4; j++) {
        float wgt = (sub < 8) ? (exv[j].x / denv[j].x) : (exv[j].y / denv[j].y);
        __half2* v2 = (__half2*)&vju[j];
        float2 a = __half22float2(v2[0]);
        float2 b = __half22float2(v2[1]);
        float2 c = __half22float2(v2[2]);
        float2 dd = __half22float2(v2[3]);
        float* p = &out[(size_t)d[j] * 128 + sub * 8];
        asm volatile("red.global.add.v4.f32 [%0], {%1, %2, %3, %4};"
                     :: "l"(p), "f"(wgt * a.x), "f"(wgt * a.y), "f"(wgt * b.x), "f"(wgt * b.y)
                     : "memory");
        asm volatile("red.global.add.v4.f32 [%0], {%1, %2, %3, %4};"
                     :: "l"(p + 4), "f"(wgt * c.x), "f"(wgt * c.y), "f"(wgt * dd.x), "f"(wgt * dd.y)
                     : "memory");
    }
}

// ---------------- launch ----------------
extern "C" void kernel_launch(void* const* d_in, const int* in_sizes, int n_in,
                              void* d_out, int out_size)
{
    const float* x           = (const float*)d_in[0];
    const float* last_update = (const float*)d_in[1];
    const int*   ei          = (const int*)  d_in[2];
    const float* t           = (const float*)d_in[3];
    const float* msg         = (const float*)d_in[4];
    const float* Wt          = (const float*)d_in[5];
    const float* bt          = (const float*)d_in[6];
    const float* Wq          = (const float*)d_in[7];
    const float* bq          = (const float*)d_in[8];
    const float* Wk          = (const float*)d_in[9];
    const float* bk          = (const float*)d_in[10];
    const float* Wv          = (const float*)d_in[11];
    const float* bv          = (const float*)d_in[12];
    const float* We          = (const float*)d_in[13];
    const float* Wskip       = (const float*)d_in[14];
    const float* bskip       = (const float*)d_in[15];
    float* out = (float*)d_out;

    cudaFuncSetAttribute(k_table,    cudaFuncAttributeMaxDynamicSharedMemorySize, TB_SMEM);
    cudaFuncSetAttribute(k_node_mma, cudaFuncAttributeMaxDynamicSharedMemorySize, NODE_SMEM);
    cudaFuncSetAttribute(k_edge_mma, cudaFuncAttributeMaxDynamicSharedMemorySize, EDGE_SMEM);

    k_prep<<<(Nn * Dd + 255) / 256, 256>>>(x, We, Wq, Wk, Wv, Wskip);

    k_table<<<296, 256, TB_SMEM>>>(Wt, bt);

    dim3 gn(74, 4);
    k_node_mma<<<gn, 256, NODE_SMEM>>>(bq, bk, bv, bskip, out);

    k_edge_mma<<<296, 512, EDGE_SMEM>>>(ei, last_update, t, msg);

    k_expsum<<<(Ee * 2 + 255) / 256, 256>>>(ei);

    k_agg<<<(AGG_CHUNK * 16 + 255) / 256, 256>>>(ei, out);
}

// round 9
// speedup vs baseline: 5.7171x; 1.0802x over previous
#include <cuda_runtime.h>
#include <cuda_fp16.h>
#include <cstdint>
#include <math.h>

#define Nn 50000
#define Ee 800000
#define Dd 128

#define TABN 65536
#define TH0  (-1000.0f)
#define HSTEP   (2000.0f / 65535.0f)
#define TSCALE  (65535.0f / 2000.0f)

// ---------------- scratch (static device globals; no allocation) ----------------
__device__ __half g_xh[(size_t)Nn * Dd];
__device__ __half g_qh[(size_t)Nn * Dd];
__device__ __half g_kh[(size_t)Nn * Dd];
__device__ __half g_vh[(size_t)Nn * Dd];
__device__ __half g_Weth[128 * 128];
__device__ __half g_Webh[128 * 128];
__device__ __half g_Wallh[512 * 128];
__device__ __half g_tab[(size_t)TABN * 128];
__device__ __half g_vj[(size_t)Ee * Dd];
__device__ float  g_alpha[Ee * 2];        // raw alpha (no exp)
// CSR by dst
__device__ int    g_cnt[Nn];
__device__ int    g_rowstart[Nn];
__device__ int    g_cursor[Nn];
__device__ int    g_csr[Ee];
__device__ int    g_bsum[256];
__device__ int    g_boff[256];

__device__ __forceinline__ uint32_t smem_u32(const void* p) {
    uint32_t a;
    asm("{ .reg .u64 t; cvta.to.shared.u64 t, %1; cvt.u32.u64 %0, t; }" : "=r"(a) : "l"(p));
    return a;
}

__device__ __forceinline__ void ldsm_x4(uint32_t* r, uint32_t addr) {
    asm volatile("ldmatrix.sync.aligned.m8n8.x4.shared.b16 {%0,%1,%2,%3}, [%4];"
                 : "=r"(r[0]), "=r"(r[1]), "=r"(r[2]), "=r"(r[3]) : "r"(addr));
}

__device__ __forceinline__ void mma16816(float* c, const uint32_t* a, const uint32_t* b) {
    asm volatile("mma.sync.aligned.m16n8k16.row.col.f32.f16.f16.f32 "
                 "{%0,%1,%2,%3}, {%4,%5,%6,%7}, {%8,%9}, {%0,%1,%2,%3};"
                 : "+f"(c[0]), "+f"(c[1]), "+f"(c[2]), "+f"(c[3])
                 : "r"(a[0]), "r"(a[1]), "r"(a[2]), "r"(a[3]), "r"(b[0]), "r"(b[1]));
}

// ---------------- prep ----------------
__global__ void k_prep(const float* __restrict__ x, const float* __restrict__ We,
                       const float* __restrict__ Wq, const float* __restrict__ Wk,
                       const float* __restrict__ Wv, const float* __restrict__ Ws)
{
    int i = blockIdx.x * blockDim.x + threadIdx.x;
    if (i < Nn * Dd) g_xh[i] = __float2half_rn(x[i]);
    if (i < 128 * 128) {
        int n = i >> 7, k = i & 127;
        g_Weth[i] = __float2half_rn(We[k * 128 + n]);
        g_Webh[i] = __float2half_rn(We[(k + 128) * 128 + n]);
    }
    if (i < 512 * 128) {
        int j = i >> 7, kk = i & 127;
        int m = j >> 7, n = j & 127;
        const float* W = (m == 0) ? Wq : (m == 1) ? Wk : (m == 2) ? Wv : Ws;
        g_Wallh[i] = __float2half_rn(W[kk * 128 + n]);
    }
    if (i < Nn) g_cnt[i] = 0;
}

// ---------------- CSR build ----------------
__global__ void k_hist(const int* __restrict__ ei) {
    int e = blockIdx.x * blockDim.x + threadIdx.x;
    if (e < Ee) atomicAdd(&g_cnt[ei[Ee + e]], 1);
}

__global__ void k_scan1() {   // 196 blocks x 256
    __shared__ int s[256];
    int i = blockIdx.x * 256 + threadIdx.x;
    int c = (i < Nn) ? g_cnt[i] : 0;
    s[threadIdx.x] = c;
    __syncthreads();
    for (int off = 1; off < 256; off <<= 1) {
        int t = (threadIdx.x >= off) ? s[threadIdx.x - off] : 0;
        __syncthreads();
        s[threadIdx.x] += t;
        __syncthreads();
    }
    if (i < Nn) g_rowstart[i] = s[threadIdx.x] - c;
    if (threadIdx.x == 255) g_bsum[blockIdx.x] = s[255];
}

__global__ void k_scan2(int nb) {   // 1 block x 256
    __shared__ int s[256];
    int c = (threadIdx.x < nb) ? g_bsum[threadIdx.x] : 0;
    s[threadIdx.x] = c;
    __syncthreads();
    for (int off = 1; off < 256; off <<= 1) {
        int t = (threadIdx.x >= off) ? s[threadIdx.x - off] : 0;
        __syncthreads();
        s[threadIdx.x] += t;
        __syncthreads();
    }
    g_boff[threadIdx.x] = s[threadIdx.x] - c;
}

__global__ void k_final() {
    int i = blockIdx.x * blockDim.x + threadIdx.x;
    if (i < Nn) {
        int r = g_rowstart[i] + g_boff[i >> 8];
        g_rowstart[i] = r;
        g_cursor[i] = r;
    }
}

__global__ void k_scatter(const int* __restrict__ ei) {
    int e = blockIdx.x * blockDim.x + threadIdx.x;
    if (e < Ee) {
        int d = ei[Ee + e];
        int pos = atomicAdd(&g_cursor[d], 1);
        g_csr[pos] = e;
    }
}

// ---------------- table build ----------------
#define TB_B_OFF 34816
#define TB_WT    69632
#define TB_BT    70144
#define TB_SMEM  70656
#define TB_TILES (TABN / 128)

__global__ void __launch_bounds__(256, 2) k_table(const float* __restrict__ Wt,
                                                  const float* __restrict__ bt)
{
    extern __shared__ char sm[];
    uint32_t sbase = smem_u32(sm);
    int tid = threadIdx.x, w = tid >> 5, l = tid & 31;
    float* sWt = (float*)(sm + TB_WT);
    float* sBt = (float*)(sm + TB_BT);

    if (tid < 128) { sWt[tid] = Wt[tid]; sBt[tid] = bt[tid]; }
    for (int c = tid; c < 2048; c += 256) {
        int row = c >> 4, kc = c & 15;
        *(uint4*)(sm + TB_B_OFF + row * 272 + kc * 16) = ((const uint4*)g_Weth)[c];
    }

    int rg = w >> 1, cg = w & 1;
    for (int tile = blockIdx.x; tile < TB_TILES; tile += gridDim.x) {
        __syncthreads();
        for (int idx = tid; idx < 8192; idx += 256) {
            int row = idx >> 6, k2 = (idx & 63) * 2;
            float th = TH0 + (float)(tile * 128 + row) * HSTEP;
            float a0 = cosf(fmaf(th, sWt[k2],     sBt[k2]));
            float a1 = cosf(fmaf(th, sWt[k2 + 1], sBt[k2 + 1]));
            *(__half2*)(sm + row * 272 + k2 * 2) = __floats2half2_rn(a0, a1);
        }
        __syncthreads();

        float acc[2][8][4];
#pragma unroll
        for (int mi = 0; mi < 2; mi++)
#pragma unroll
            for (int nb = 0; nb < 8; nb++)
#pragma unroll
                for (int j = 0; j < 4; j++) acc[mi][nb][j] = 0.0f;

#pragma unroll
        for (int ks = 0; ks < 8; ks++) {
            uint32_t af[2][4];
#pragma unroll
            for (int mi = 0; mi < 2; mi++) {
                uint32_t addr = sbase + (uint32_t)(rg * 32 + mi * 16 + (l & 15)) * 272
                              + ks * 32 + (l >> 4) * 16;
                ldsm_x4(af[mi], addr);
            }
            uint32_t bf[8][2];
#pragma unroll
            for (int nbp = 0; nbp < 4; nbp++) {
                uint32_t r[4];
                int n = cg * 64 + nbp * 16 + (l & 7) + ((l >> 4) << 3);
                uint32_t addr = sbase + TB_B_OFF + (uint32_t)n * 272
                              + ks * 32 + ((l >> 3) & 1) * 16;
                ldsm_x4(r, addr);
                bf[nbp * 2][0] = r[0]; bf[nbp * 2][1] = r[1];
                bf[nbp * 2 + 1][0] = r[2]; bf[nbp * 2 + 1][1] = r[3];
            }
#pragma unroll
            for (int mi = 0; mi < 2; mi++)
#pragma unroll
                for (int nb = 0; nb < 8; nb++)
                    mma16816(acc[mi][nb], af[mi], bf[nb]);
        }

#pragma unroll
        for (int mi = 0; mi < 2; mi++) {
            int r0 = tile * 128 + rg * 32 + mi * 16 + (l >> 2);
#pragma unroll
            for (int nb = 0; nb < 8; nb++) {
                int col = cg * 64 + nb * 8 + 2 * (l & 3);
                *(__half2*)&g_tab[(size_t)r0 * 128 + col] =
                    __floats2half2_rn(acc[mi][nb][0], acc[mi][nb][1]);
                *(__half2*)&g_tab[(size_t)(r0 + 8) * 128 + col] =
                    __floats2half2_rn(acc[mi][nb][2], acc[mi][nb][3]);
            }
        }
    }
}

// ---------------- node GEMM ----------------
#define NODE_B_OFF 34816
#define NODE_SMEM  69632
#define N_TILES    391

__global__ void __launch_bounds__(256, 2) k_node_mma(
    const float* __restrict__ bq, const float* __restrict__ bk,
    const float* __restrict__ bv, const float* __restrict__ bs,
    float* __restrict__ out)
{
    extern __shared__ char sm[];
    uint32_t sbase = smem_u32(sm);
    int tid = threadIdx.x, w = tid >> 5, l = tid & 31;
    int mat = blockIdx.y;

    const __half* Wsrc = g_Wallh + (size_t)mat * 128 * 128;
    for (int c = tid; c < 2048; c += 256) {
        int row = c >> 4, kc = c & 15;
        *(uint4*)(sm + NODE_B_OFF + row * 272 + kc * 16) = ((const uint4*)Wsrc)[c];
    }

    int rg = w >> 1, cg = w & 1;
    for (int tile = blockIdx.x; tile < N_TILES; tile += gridDim.x) {
        int n0 = tile * 128;
        __syncthreads();
        for (int c = tid; c < 2048; c += 256) {
            int row = c >> 4, kc = c & 15;
            int nr = n0 + row;
            uint4 v = make_uint4(0, 0, 0, 0);
            if (nr < Nn) v = ((const uint4*)g_xh)[((size_t)nr * 128) / 8 + kc];
            *(uint4*)(sm + row * 272 + kc * 16) = v;
        }
        __syncthreads();

        float acc[2][8][4];
#pragma unroll
        for (int mi = 0; mi < 2; mi++)
#pragma unroll
            for (int nb = 0; nb < 8; nb++)
#pragma unroll
                for (int j = 0; j < 4; j++) acc[mi][nb][j] = 0.0f;

#pragma unroll
        for (int ks = 0; ks < 8; ks++) {
            uint32_t af[2][4];
#pragma unroll
            for (int mi = 0; mi < 2; mi++) {
                uint32_t addr = sbase + (uint32_t)(rg * 32 + mi * 16 + (l & 15)) * 272
                              + ks * 32 + (l >> 4) * 16;
                ldsm_x4(af[mi], addr);
            }
            uint32_t bf[8][2];
#pragma unroll
            for (int nbp = 0; nbp < 4; nbp++) {
                uint32_t r[4];
                int n = cg * 64 + nbp * 16 + (l & 7) + ((l >> 4) << 3);
                uint32_t addr = sbase + NODE_B_OFF + (uint32_t)n * 272
                              + ks * 32 + ((l >> 3) & 1) * 16;
                ldsm_x4(r, addr);
                bf[nbp * 2][0] = r[0]; bf[nbp * 2][1] = r[1];
                bf[nbp * 2 + 1][0] = r[2]; bf[nbp * 2 + 1][1] = r[3];
            }
#pragma unroll
            for (int mi = 0; mi < 2; mi++)
#pragma unroll
                for (int nb = 0; nb < 8; nb++)
                    mma16816(acc[mi][nb], af[mi], bf[nb]);
        }

        const float* bias = (mat == 0) ? bq : (mat == 1) ? bk : (mat == 2) ? bv : bs;
#pragma unroll
        for (int mi = 0; mi < 2; mi++) {
            int r0 = n0 + rg * 32 + mi * 16 + (l >> 2);
#pragma unroll
            for (int nb = 0; nb < 8; nb++) {
                int col = cg * 64 + nb * 8 + 2 * (l & 3);
                float2 bi = *(const float2*)&bias[col];
                if (mat == 3) {
                    if (r0 < Nn)
                        *(float2*)&out[(size_t)r0 * 128 + col] =
                            make_float2(acc[mi][nb][0] + bi.x, acc[mi][nb][1] + bi.y);
                    if (r0 + 8 < Nn)
                        *(float2*)&out[(size_t)(r0 + 8) * 128 + col] =
                            make_float2(acc[mi][nb][2] + bi.x, acc[mi][nb][3] + bi.y);
                } else {
                    __half* dst = (mat == 0) ? g_qh : (mat == 1) ? g_kh : g_vh;
                    if (r0 < Nn)
                        *(__half2*)&dst[(size_t)r0 * 128 + col] =
                            __floats2half2_rn(acc[mi][nb][0] + bi.x, acc[mi][nb][1] + bi.y);
                    if (r0 + 8 < Nn)
                        *(__half2*)&dst[(size_t)(r0 + 8) * 128 + col] =
                            __floats2half2_rn(acc[mi][nb][2] + bi.x, acc[mi][nb][3] + bi.y);
                }
            }
        }
    }
}

// ---------------- edge GEMM: 512 threads, warp tile 32x32 ----------------
#define E_B_OFF   34816
#define E_SRC     69632
#define E_DST     70144
#define E_RLT     70656
#define EDGE_SMEM 71168
#define E_TILES   (Ee / 128)

__global__ void __launch_bounds__(512, 2) k_edge_mma(
    const int*   __restrict__ ei,
    const float* __restrict__ last_update,
    const float* __restrict__ t,
    const float* __restrict__ msg)
{
    extern __shared__ char sm[];
    uint32_t sbase = smem_u32(sm);
    int tid = threadIdx.x, w = tid >> 5, l = tid & 31;

    int*   sSrc = (int*)(sm + E_SRC);
    int*   sDst = (int*)(sm + E_DST);
    float* sRlt = (float*)(sm + E_RLT);

    for (int c = tid; c < 2048; c += 512) {
        int row = c >> 4, kc = c & 15;
        *(uint4*)(sm + E_B_OFF + row * 272 + kc * 16) = ((const uint4*)g_Webh)[c];
    }

    int rg = w >> 2, cg = w & 3;
    for (int tile = blockIdx.x; tile < E_TILES; tile += gridDim.x) {
        __syncthreads();
        if (tid < 128) {
            int e = tile * 128 + tid;
            int s = ei[e];
            sSrc[tid] = s;
            sDst[tid] = ei[Ee + e];
            sRlt[tid] = last_update[s] - t[e];
        }
        for (int c = tid; c < 2048; c += 512) {
            int row = c >> 4, kc = c & 15;
            const float4* mp = (const float4*)(msg + (size_t)(tile * 128 + row) * 128 + kc * 8);
            float4 m0 = mp[0], m1 = mp[1];
            __half2 h[4];
            h[0] = __floats2half2_rn(m0.x, m0.y); h[1] = __floats2half2_rn(m0.z, m0.w);
            h[2] = __floats2half2_rn(m1.x, m1.y); h[3] = __floats2half2_rn(m1.z, m1.w);
            *(uint4*)(sm + row * 272 + kc * 16) = *(uint4*)h;
        }
        __syncthreads();

        float acc[2][4][4];
#pragma unroll
        for (int mi = 0; mi < 2; mi++)
#pragma unroll
            for (int nb = 0; nb < 4; nb++)
#pragma unroll
                for (int j = 0; j < 4; j++) acc[mi][nb][j] = 0.0f;

#pragma unroll
        for (int ks = 0; ks < 8; ks++) {
            uint32_t af[2][4];
#pragma unroll
            for (int mi = 0; mi < 2; mi++) {
                uint32_t addr = sbase + (uint32_t)(rg * 32 + mi * 16 + (l & 15)) * 272
                              + ks * 32 + (l >> 4) * 16;
                ldsm_x4(af[mi], addr);
            }
            uint32_t bf[4][2];
#pragma unroll
            for (int nbp = 0; nbp < 2; nbp++) {
                uint32_t r[4];
                int n = cg * 32 + nbp * 16 + (l & 7) + ((l >> 4) << 3);
                uint32_t addr = sbase + E_B_OFF + (uint32_t)n * 272
                              + ks * 32 + ((l >> 3) & 1) * 16;
                ldsm_x4(r, addr);
                bf[nbp * 2][0] = r[0]; bf[nbp * 2][1] = r[1];
                bf[nbp * 2 + 1][0] = r[2]; bf[nbp * 2 + 1][1] = r[3];
            }
#pragma unroll
            for (int mi = 0; mi < 2; mi++)
#pragma unroll
                for (int nb = 0; nb < 4; nb++)
                    mma16816(acc[mi][nb], af[mi], bf[nb]);
        }
        __syncthreads();

#pragma unroll
        for (int mi = 0; mi < 2; mi++) {
            int r0 = rg * 32 + mi * 16 + (l >> 2);
#pragma unroll
            for (int nb = 0; nb < 4; nb++) {
                int col = cg * 32 + nb * 8 + 2 * (l & 3);
                *(__half2*)(sm + r0 * 272 + col * 2) =
                    __floats2half2_rn(acc[mi][nb][0], acc[mi][nb][1]);
                *(__half2*)(sm + (r0 + 8) * 272 + col * 2) =
                    __floats2half2_rn(acc[mi][nb][2], acc[mi][nb][3]);
            }
        }
        __syncthreads();

        // epilogue: 8 lanes per (edge, half) task
        {
            int group = l >> 3, sub = l & 7;
#pragma unroll
            for (int it = 0; it < 4; it++) {
                int T = w * 16 + it * 4 + group;
                int el = T >> 1, hf = T & 1;
                int e = tile * 128 + el;
                int s = sSrc[el], d = sDst[el];
                (void)d;

                float f = (sRlt[el] - TH0) * TSCALE;
                int i0 = (int)f;
                i0 = max(0, min(i0, TABN - 2));
                float fr = f - (float)i0;

                int cb = hf * 64 + sub * 8;

                uint4 cu  = *(const uint4*)(sm + el * 272 + cb * 2);
                uint4 qu  = *(const uint4*)(g_qh + (size_t)sDst[el] * 128 + cb);
                uint4 ku  = *(const uint4*)(g_kh + (size_t)s * 128 + cb);
                uint4 vu  = *(const uint4*)(g_vh + (size_t)s * 128 + cb);
                uint4 g0u = *(const uint4*)(g_tab + (size_t)i0 * 128 + cb);
                uint4 g1u = *(const uint4*)(g_tab + (size_t)(i0 + 1) * 128 + cb);

                __half2* q2  = (__half2*)&qu;
                __half2* k2  = (__half2*)&ku;
                __half2* v2  = (__half2*)&vu;
                __half2* c2  = (__half2*)&cu;
                __half2* g02 = (__half2*)&g0u;
                __half2* g12 = (__half2*)&g1u;

                float dot = 0.0f;
                __half2 o2[4];
#pragma unroll
                for (int j = 0; j < 4; j++) {
                    float2 cf = __half22float2(c2[j]);
                    float2 ga = __half22float2(g02[j]);
                    float2 gb = __half22float2(g12[j]);
                    float ea = cf.x + ga.x + fr * (gb.x - ga.x);
                    float eb = cf.y + ga.y + fr * (gb.y - ga.y);
                    float2 qf = __half22float2(q2[j]);
                    float2 kf = __half22float2(k2[j]);
                    float2 vf = __half22float2(v2[j]);
                    dot = fmaf(qf.x, kf.x + ea, dot);
                    dot = fmaf(qf.y, kf.y + eb, dot);
                    o2[j] = __floats2half2_rn(vf.x + ea, vf.y + eb);
                }
                *(uint4*)(g_vj + (size_t)e * 128 + cb) = *(uint4*)o2;

                dot += __shfl_xor_sync(0xffffffffu, dot, 1);
                dot += __shfl_xor_sync(0xffffffffu, dot, 2);
                dot += __shfl_xor_sync(0xffffffffu, dot, 4);
                if (sub == 0) g_alpha[e * 2 + hf] = dot * 0.125f;
            }
        }
    }
}

// ---------------- CSR softmax + aggregation: 16 lanes per node ----------------
__global__ void __launch_bounds__(256) k_aggcsr(float* __restrict__ out)
{
    int tid = blockIdx.x * blockDim.x + threadIdx.x;
    int g = tid >> 4, sub = tid & 15;
    if (g >= Nn) return;
    int beg = g_rowstart[g];
    int end = beg + g_cnt[g];
    if (end <= beg) return;

    // pass 1: per-head max
    float m0 = -INFINITY, m1 = -INFINITY;
    for (int p = beg + sub; p < end; p += 16) {
        int e = g_csr[p];
        float2 al = *(const float2*)&g_alpha[e * 2];
        m0 = fmaxf(m0, al.x);
        m1 = fmaxf(m1, al.y);
    }
#pragma unroll
    for (int s = 1; s < 16; s <<= 1) {
        m0 = fmaxf(m0, __shfl_xor_sync(0xffffffffu, m0, s, 16));
        m1 = fmaxf(m1, __shfl_xor_sync(0xffffffffu, m1, s, 16));
    }

    // pass 2: exp + sum (first 4 chunks cached in regs)
    float ex0[4], ex1[4];
    float s0 = 0.0f, s1 = 0.0f;
    int nch = min((end - beg + 15) >> 4, 4);
#pragma unroll
    for (int c = 0; c < 4; c++) { ex0[c] = 0.0f; ex1[c] = 0.0f; }
    for (int c = 0; c < nch; c++) {
        int p = beg + c * 16 + sub;
        float a0 = 0.0f, a1 = 0.0f;
        if (p < end) {
            int e = g_csr[p];
            float2 al = *(const float2*)&g_alpha[e * 2];
            a0 = expf(al.x - m0);
            a1 = expf(al.y - m1);
        }
        ex0[c] = a0; ex1[c] = a1;
        s0 += a0; s1 += a1;
    }
    for (int p = beg + 64 + sub; p < end; p += 16) {   // rare overflow (>64 edges)
        int e = g_csr[p];
        float2 al = *(const float2*)&g_alpha[e * 2];
        s0 += expf(al.x - m0);
        s1 += expf(al.y - m1);
    }
#pragma unroll
    for (int s = 1; s < 16; s <<= 1) {
        s0 += __shfl_xor_sync(0xffffffffu, s0, s, 16);
        s1 += __shfl_xor_sync(0xffffffffu, s1, s, 16);
    }
    float inv = (sub < 8) ? (1.0f / s0) : (1.0f / s1);

    // pass 3: weighted vj accumulation
    float acc[8];
#pragma unroll
    for (int j = 0; j < 8; j++) acc[j] = 0.0f;

    for (int c = 0; c < nch; c++) {
#pragma unroll
        for (int j = 0; j < 16; j++) {
            int p = beg + c * 16 + j;
            float A = __shfl_sync(0xffffffffu, ex0[c], j, 16);
            float B = __shfl_sync(0xffffffffu, ex1[c], j, 16);
            if (p >= end) break;
            float wv = ((sub < 8) ? A : B) * inv;
            int e = g_csr[p];
            uint4 vju = *(const uint4*)(g_vj + (size_t)e * 128 + sub * 8);
            __half2* v2 = (__half2*)&vju;
#pragma unroll
            for (int q = 0; q < 4; q++) {
                float2 vf = __half22float2(v2[q]);
                acc[q * 2]     = fmaf(wv, vf.x, acc[q * 2]);
                acc[q * 2 + 1] = fmaf(wv, vf.y, acc[q * 2 + 1]);
            }
        }
    }
    for (int p = beg + 64; p < end; p++) {             // overflow: recompute exp
        int e = g_csr[p];
        float2 al = *(const float2*)&g_alpha[e * 2];
        float wv = ((sub < 8) ? expf(al.x - m0) : expf(al.y - m1)) * inv;
        uint4 vju = *(const uint4*)(g_vj + (size_t)e * 128 + sub * 8);
        __half2* v2 = (__half2*)&vju;
#pragma unroll
        for (int q = 0; q < 4; q++) {
            float2 vf = __half22float2(v2[q]);
            acc[q * 2]     = fmaf(wv, vf.x, acc[q * 2]);
            acc[q * 2 + 1] = fmaf(wv, vf.y, acc[q * 2 + 1]);
        }
    }

    float4* op = (float4*)&out[(size_t)g * 128 + sub * 8];
    float4 o0 = op[0], o1 = op[1];
    o0.x += acc[0]; o0.y += acc[1]; o0.z += acc[2]; o0.w += acc[3];
    o1.x += acc[4]; o1.y += acc[5]; o1.z += acc[6]; o1.w += acc[7];
    op[0] = o0; op[1] = o1;
}

// ---------------- launch ----------------
extern "C" void kernel_launch(void* const* d_in, const int* in_sizes, int n_in,
                              void* d_out, int out_size)
{
    const float* x           = (const float*)d_in[0];
    const float* last_update = (const float*)d_in[1];
    const int*   ei          = (const int*)  d_in[2];
    const float* t           = (const float*)d_in[3];
    const float* msg         = (const float*)d_in[4];
    const float* Wt          = (const float*)d_in[5];
    const float* bt          = (const float*)d_in[6];
    const float* Wq          = (const float*)d_in[7];
    const float* bq          = (const float*)d_in[8];
    const float* Wk          = (const float*)d_in[9];
    const float* bk          = (const float*)d_in[10];
    const float* Wv          = (const float*)d_in[11];
    const float* bv          = (const float*)d_in[12];
    const float* We          = (const float*)d_in[13];
    const float* Wskip       = (const float*)d_in[14];
    const float* bskip       = (const float*)d_in[15];
    float* out = (float*)d_out;

    cudaFuncSetAttribute(k_table,    cudaFuncAttributeMaxDynamicSharedMemorySize, TB_SMEM);
    cudaFuncSetAttribute(k_node_mma, cudaFuncAttributeMaxDynamicSharedMemorySize, NODE_SMEM);
    cudaFuncSetAttribute(k_edge_mma, cudaFuncAttributeMaxDynamicSharedMemorySize, EDGE_SMEM);

    const int NB1 = (Nn + 255) / 256;   // 196

    k_prep<<<(Nn * Dd + 255) / 256, 256>>>(x, We, Wq, Wk, Wv, Wskip);

    k_hist<<<(Ee + 255) / 256, 256>>>(ei);
    k_scan1<<<NB1, 256>>>();
    k_scan2<<<1, 256>>>(NB1);
    k_final<<<NB1, 256>>>();
    k_scatter<<<(Ee + 255) / 256, 256>>>(ei);

    k_table<<<296, 256, TB_SMEM>>>(Wt, bt);

    dim3 gn(74, 4);
    k_node_mma<<<gn, 256, NODE_SMEM>>>(bq, bk, bv, bskip, out);

    k_edge_mma<<<296, 512, EDGE_SMEM>>>(ei, last_update, t, msg);

    k_aggcsr<<<(Nn * 16 + 255) / 256, 256>>>(out);
}

// round 10
// speedup vs baseline: 5.7641x; 1.0082x over previous
#include <cuda_runtime.h>
#include <cuda_fp16.h>
#include <cstdint>
#include <math.h>

#define Nn 50000
#define Ee 800000
#define Dd 128

#define TABN 65536
#define TH0  (-1000.0f)
#define HSTEP   (2000.0f / 65535.0f)
#define TSCALE  (65535.0f / 2000.0f)

// ---------------- scratch (static device globals; no allocation) ----------------
__device__ __half g_xh[(size_t)Nn * Dd];
__device__ __half g_qh[(size_t)Nn * Dd];
__device__ __half g_kh[(size_t)Nn * Dd];
__device__ __half g_vh[(size_t)Nn * Dd];
__device__ __half g_Weth[128 * 128];
__device__ __half g_Webh[128 * 128];
__device__ __half g_Wallh[512 * 128];
__device__ __half g_tab[(size_t)TABN * 128];
__device__ __half g_vj[(size_t)Ee * Dd];   // CSR-ordered: slot-major
__device__ float  g_alpha[Ee * 2];         // CSR-ordered: [slot][head]
// CSR by dst
__device__ int    g_cnt[Nn];
__device__ int    g_rowstart[Nn];
__device__ int    g_cursor[Nn];
__device__ int    g_slot[Ee];              // edge -> CSR slot
__device__ int    g_bsum[256];
__device__ int    g_boff[256];

__device__ __forceinline__ uint32_t smem_u32(const void* p) {
    uint32_t a;
    asm("{ .reg .u64 t; cvta.to.shared.u64 t, %1; cvt.u32.u64 %0, t; }" : "=r"(a) : "l"(p));
    return a;
}

__device__ __forceinline__ void ldsm_x4(uint32_t* r, uint32_t addr) {
    asm volatile("ldmatrix.sync.aligned.m8n8.x4.shared.b16 {%0,%1,%2,%3}, [%4];"
                 : "=r"(r[0]), "=r"(r[1]), "=r"(r[2]), "=r"(r[3]) : "r"(addr));
}

__device__ __forceinline__ void mma16816(float* c, const uint32_t* a, const uint32_t* b) {
    asm volatile("mma.sync.aligned.m16n8k16.row.col.f32.f16.f16.f32 "
                 "{%0,%1,%2,%3}, {%4,%5,%6,%7}, {%8,%9}, {%0,%1,%2,%3};"
                 : "+f"(c[0]), "+f"(c[1]), "+f"(c[2]), "+f"(c[3])
                 : "r"(a[0]), "r"(a[1]), "r"(a[2]), "r"(a[3]), "r"(b[0]), "r"(b[1]));
}

// ---------------- prep ----------------
__global__ void k_prep(const float* __restrict__ x, const float* __restrict__ We,
                       const float* __restrict__ Wq, const float* __restrict__ Wk,
                       const float* __restrict__ Wv, const float* __restrict__ Ws)
{
    int i = blockIdx.x * blockDim.x + threadIdx.x;
    if (i < Nn * Dd) g_xh[i] = __float2half_rn(x[i]);
    if (i < 128 * 128) {
        int n = i >> 7, k = i & 127;
        g_Weth[i] = __float2half_rn(We[k * 128 + n]);
        g_Webh[i] = __float2half_rn(We[(k + 128) * 128 + n]);
    }
    if (i < 512 * 128) {
        int j = i >> 7, kk = i & 127;
        int m = j >> 7, n = j & 127;
        const float* W = (m == 0) ? Wq : (m == 1) ? Wk : (m == 2) ? Wv : Ws;
        g_Wallh[i] = __float2half_rn(W[kk * 128 + n]);
    }
    if (i < Nn) g_cnt[i] = 0;
}

// ---------------- CSR build ----------------
__global__ void k_hist(const int* __restrict__ ei) {
    int e = blockIdx.x * blockDim.x + threadIdx.x;
    if (e < Ee) atomicAdd(&g_cnt[ei[Ee + e]], 1);
}

__global__ void k_scan1() {
    __shared__ int s[256];
    int i = blockIdx.x * 256 + threadIdx.x;
    int c = (i < Nn) ? g_cnt[i] : 0;
    s[threadIdx.x] = c;
    __syncthreads();
    for (int off = 1; off < 256; off <<= 1) {
        int t = (threadIdx.x >= off) ? s[threadIdx.x - off] : 0;
        __syncthreads();
        s[threadIdx.x] += t;
        __syncthreads();
    }
    if (i < Nn) g_rowstart[i] = s[threadIdx.x] - c;
    if (threadIdx.x == 255) g_bsum[blockIdx.x] = s[255];
}

__global__ void k_scan2(int nb) {
    __shared__ int s[256];
    int c = (threadIdx.x < nb) ? g_bsum[threadIdx.x] : 0;
    s[threadIdx.x] = c;
    __syncthreads();
    for (int off = 1; off < 256; off <<= 1) {
        int t = (threadIdx.x >= off) ? s[threadIdx.x - off] : 0;
        __syncthreads();
        s[threadIdx.x] += t;
        __syncthreads();
    }
    g_boff[threadIdx.x] = s[threadIdx.x] - c;
}

__global__ void k_final() {
    int i = blockIdx.x * blockDim.x + threadIdx.x;
    if (i < Nn) {
        int r = g_rowstart[i] + g_boff[i >> 8];
        g_rowstart[i] = r;
        g_cursor[i] = r;
    }
}

__global__ void k_scatter(const int* __restrict__ ei) {
    int e = blockIdx.x * blockDim.x + threadIdx.x;
    if (e < Ee) {
        int d = ei[Ee + e];
        int pos = atomicAdd(&g_cursor[d], 1);
        g_slot[e] = pos;
    }
}

// ---------------- table build ----------------
#define TB_B_OFF 34816
#define TB_WT    69632
#define TB_BT    70144
#define TB_SMEM  70656
#define TB_TILES (TABN / 128)

__global__ void __launch_bounds__(256, 2) k_table(const float* __restrict__ Wt,
                                                  const float* __restrict__ bt)
{
    extern __shared__ char sm[];
    uint32_t sbase = smem_u32(sm);
    int tid = threadIdx.x, w = tid >> 5, l = tid & 31;
    float* sWt = (float*)(sm + TB_WT);
    float* sBt = (float*)(sm + TB_BT);

    if (tid < 128) { sWt[tid] = Wt[tid]; sBt[tid] = bt[tid]; }
    for (int c = tid; c < 2048; c += 256) {
        int row = c >> 4, kc = c & 15;
        *(uint4*)(sm + TB_B_OFF + row * 272 + kc * 16) = ((const uint4*)g_Weth)[c];
    }

    int rg = w >> 1, cg = w & 1;
    for (int tile = blockIdx.x; tile < TB_TILES; tile += gridDim.x) {
        __syncthreads();
        for (int idx = tid; idx < 8192; idx += 256) {
            int row = idx >> 6, k2 = (idx & 63) * 2;
            float th = TH0 + (float)(tile * 128 + row) * HSTEP;
            float a0 = cosf(fmaf(th, sWt[k2],     sBt[k2]));
            float a1 = cosf(fmaf(th, sWt[k2 + 1], sBt[k2 + 1]));
            *(__half2*)(sm + row * 272 + k2 * 2) = __floats2half2_rn(a0, a1);
        }
        __syncthreads();

        float acc[2][8][4];
#pragma unroll
        for (int mi = 0; mi < 2; mi++)
#pragma unroll
            for (int nb = 0; nb < 8; nb++)
#pragma unroll
                for (int j = 0; j < 4; j++) acc[mi][nb][j] = 0.0f;

#pragma unroll
        for (int ks = 0; ks < 8; ks++) {
            uint32_t af[2][4];
#pragma unroll
            for (int mi = 0; mi < 2; mi++) {
                uint32_t addr = sbase + (uint32_t)(rg * 32 + mi * 16 + (l & 15)) * 272
                              + ks * 32 + (l >> 4) * 16;
                ldsm_x4(af[mi], addr);
            }
            uint32_t bf[8][2];
#pragma unroll
            for (int nbp = 0; nbp < 4; nbp++) {
                uint32_t r[4];
                int n = cg * 64 + nbp * 16 + (l & 7) + ((l >> 4) << 3);
                uint32_t addr = sbase + TB_B_OFF + (uint32_t)n * 272
                              + ks * 32 + ((l >> 3) & 1) * 16;
                ldsm_x4(r, addr);
                bf[nbp * 2][0] = r[0]; bf[nbp * 2][1] = r[1];
                bf[nbp * 2 + 1][0] = r[2]; bf[nbp * 2 + 1][1] = r[3];
            }
#pragma unroll
            for (int mi = 0; mi < 2; mi++)
#pragma unroll
                for (int nb = 0; nb < 8; nb++)
                    mma16816(acc[mi][nb], af[mi], bf[nb]);
        }

#pragma unroll
        for (int mi = 0; mi < 2; mi++) {
            int r0 = tile * 128 + rg * 32 + mi * 16 + (l >> 2);
#pragma unroll
            for (int nb = 0; nb < 8; nb++) {
                int col = cg * 64 + nb * 8 + 2 * (l & 3);
                *(__half2*)&g_tab[(size_t)r0 * 128 + col] =
                    __floats2half2_rn(acc[mi][nb][0], acc[mi][nb][1]);
                *(__half2*)&g_tab[(size_t)(r0 + 8) * 128 + col] =
                    __floats2half2_rn(acc[mi][nb][2], acc[mi][nb][3]);
            }
        }
    }
}

// ---------------- node GEMM ----------------
#define NODE_B_OFF 34816
#define NODE_SMEM  69632
#define N_TILES    391

__global__ void __launch_bounds__(256, 2) k_node_mma(
    const float* __restrict__ bq, const float* __restrict__ bk,
    const float* __restrict__ bv, const float* __restrict__ bs,
    float* __restrict__ out)
{
    extern __shared__ char sm[];
    uint32_t sbase = smem_u32(sm);
    int tid = threadIdx.x, w = tid >> 5, l = tid & 31;
    int mat = blockIdx.y;

    const __half* Wsrc = g_Wallh + (size_t)mat * 128 * 128;
    for (int c = tid; c < 2048; c += 256) {
        int row = c >> 4, kc = c & 15;
        *(uint4*)(sm + NODE_B_OFF + row * 272 + kc * 16) = ((const uint4*)Wsrc)[c];
    }

    int rg = w >> 1, cg = w & 1;
    for (int tile = blockIdx.x; tile < N_TILES; tile += gridDim.x) {
        int n0 = tile * 128;
        __syncthreads();
        for (int c = tid; c < 2048; c += 256) {
            int row = c >> 4, kc = c & 15;
            int nr = n0 + row;
            uint4 v = make_uint4(0, 0, 0, 0);
            if (nr < Nn) v = ((const uint4*)g_xh)[((size_t)nr * 128) / 8 + kc];
            *(uint4*)(sm + row * 272 + kc * 16) = v;
        }
        __syncthreads();

        float acc[2][8][4];
#pragma unroll
        for (int mi = 0; mi < 2; mi++)
#pragma unroll
            for (int nb = 0; nb < 8; nb++)
#pragma unroll
                for (int j = 0; j < 4; j++) acc[mi][nb][j] = 0.0f;

#pragma unroll
        for (int ks = 0; ks < 8; ks++) {
            uint32_t af[2][4];
#pragma unroll
            for (int mi = 0; mi < 2; mi++) {
                uint32_t addr = sbase + (uint32_t)(rg * 32 + mi * 16 + (l & 15)) * 272
                              + ks * 32 + (l >> 4) * 16;
                ldsm_x4(af[mi], addr);
            }
            uint32_t bf[8][2];
#pragma unroll
            for (int nbp = 0; nbp < 4; nbp++) {
                uint32_t r[4];
                int n = cg * 64 + nbp * 16 + (l & 7) + ((l >> 4) << 3);
                uint32_t addr = sbase + NODE_B_OFF + (uint32_t)n * 272
                              + ks * 32 + ((l >> 3) & 1) * 16;
                ldsm_x4(r, addr);
                bf[nbp * 2][0] = r[0]; bf[nbp * 2][1] = r[1];
                bf[nbp * 2 + 1][0] = r[2]; bf[nbp * 2 + 1][1] = r[3];
            }
#pragma unroll
            for (int mi = 0; mi < 2; mi++)
#pragma unroll
                for (int nb = 0; nb < 8; nb++)
                    mma16816(acc[mi][nb], af[mi], bf[nb]);
        }

        const float* bias = (mat == 0) ? bq : (mat == 1) ? bk : (mat == 2) ? bv : bs;
#pragma unroll
        for (int mi = 0; mi < 2; mi++) {
            int r0 = n0 + rg * 32 + mi * 16 + (l >> 2);
#pragma unroll
            for (int nb = 0; nb < 8; nb++) {
                int col = cg * 64 + nb * 8 + 2 * (l & 3);
                float2 bi = *(const float2*)&bias[col];
                if (mat == 3) {
                    if (r0 < Nn)
                        *(float2*)&out[(size_t)r0 * 128 + col] =
                            make_float2(acc[mi][nb][0] + bi.x, acc[mi][nb][1] + bi.y);
                    if (r0 + 8 < Nn)
                        *(float2*)&out[(size_t)(r0 + 8) * 128 + col] =
                            make_float2(acc[mi][nb][2] + bi.x, acc[mi][nb][3] + bi.y);
                } else {
                    __half* dst = (mat == 0) ? g_qh : (mat == 1) ? g_kh : g_vh;
                    if (r0 < Nn)
                        *(__half2*)&dst[(size_t)r0 * 128 + col] =
                            __floats2half2_rn(acc[mi][nb][0] + bi.x, acc[mi][nb][1] + bi.y);
                    if (r0 + 8 < Nn)
                        *(__half2*)&dst[(size_t)(r0 + 8) * 128 + col] =
                            __floats2half2_rn(acc[mi][nb][2] + bi.x, acc[mi][nb][3] + bi.y);
                }
            }
        }
    }
}

// ---------------- edge GEMM: 512 threads, warp tile 32x32, slot-ordered output ----------------
#define E_B_OFF   34816
#define E_SRC     69632
#define E_DST     70144
#define E_RLT     70656
#define E_SLOT    71168
#define EDGE_SMEM 71680
#define E_TILES   (Ee / 128)

__global__ void __launch_bounds__(512, 2) k_edge_mma(
    const int*   __restrict__ ei,
    const float* __restrict__ last_update,
    const float* __restrict__ t,
    const float* __restrict__ msg)
{
    extern __shared__ char sm[];
    uint32_t sbase = smem_u32(sm);
    int tid = threadIdx.x, w = tid >> 5, l = tid & 31;

    int*   sSrc  = (int*)(sm + E_SRC);
    int*   sDst  = (int*)(sm + E_DST);
    float* sRlt  = (float*)(sm + E_RLT);
    int*   sSlot = (int*)(sm + E_SLOT);

    for (int c = tid; c < 2048; c += 512) {
        int row = c >> 4, kc = c & 15;
        *(uint4*)(sm + E_B_OFF + row * 272 + kc * 16) = ((const uint4*)g_Webh)[c];
    }

    int rg = w >> 2, cg = w & 3;
    for (int tile = blockIdx.x; tile < E_TILES; tile += gridDim.x) {
        __syncthreads();
        if (tid < 128) {
            int e = tile * 128 + tid;
            int s = ei[e];
            sSrc[tid]  = s;
            sDst[tid]  = ei[Ee + e];
            sRlt[tid]  = last_update[s] - t[e];
            sSlot[tid] = g_slot[e];
        }
        for (int c = tid; c < 2048; c += 512) {
            int row = c >> 4, kc = c & 15;
            const float4* mp = (const float4*)(msg + (size_t)(tile * 128 + row) * 128 + kc * 8);
            float4 m0 = mp[0], m1 = mp[1];
            __half2 h[4];
            h[0] = __floats2half2_rn(m0.x, m0.y); h[1] = __floats2half2_rn(m0.z, m0.w);
            h[2] = __floats2half2_rn(m1.x, m1.y); h[3] = __floats2half2_rn(m1.z, m1.w);
            *(uint4*)(sm + row * 272 + kc * 16) = *(uint4*)h;
        }
        __syncthreads();

        float acc[2][4][4];
#pragma unroll
        for (int mi = 0; mi < 2; mi++)
#pragma unroll
            for (int nb = 0; nb < 4; nb++)
#pragma unroll
                for (int j = 0; j < 4; j++) acc[mi][nb][j] = 0.0f;

#pragma unroll
        for (int ks = 0; ks < 8; ks++) {
            uint32_t af[2][4];
#pragma unroll
            for (int mi = 0; mi < 2; mi++) {
                uint32_t addr = sbase + (uint32_t)(rg * 32 + mi * 16 + (l & 15)) * 272
                              + ks * 32 + (l >> 4) * 16;
                ldsm_x4(af[mi], addr);
            }
            uint32_t bf[4][2];
#pragma unroll
            for (int nbp = 0; nbp < 2; nbp++) {
                uint32_t r[4];
                int n = cg * 32 + nbp * 16 + (l & 7) + ((l >> 4) << 3);
                uint32_t addr = sbase + E_B_OFF + (uint32_t)n * 272
                              + ks * 32 + ((l >> 3) & 1) * 16;
                ldsm_x4(r, addr);
                bf[nbp * 2][0] = r[0]; bf[nbp * 2][1] = r[1];
                bf[nbp * 2 + 1][0] = r[2]; bf[nbp * 2 + 1][1] = r[3];
            }
#pragma unroll
            for (int mi = 0; mi < 2; mi++)
#pragma unroll
                for (int nb = 0; nb < 4; nb++)
                    mma16816(acc[mi][nb], af[mi], bf[nb]);
        }
        __syncthreads();

#pragma unroll
        for (int mi = 0; mi < 2; mi++) {
            int r0 = rg * 32 + mi * 16 + (l >> 2);
#pragma unroll
            for (int nb = 0; nb < 4; nb++) {
                int col = cg * 32 + nb * 8 + 2 * (l & 3);
                *(__half2*)(sm + r0 * 272 + col * 2) =
                    __floats2half2_rn(acc[mi][nb][0], acc[mi][nb][1]);
                *(__half2*)(sm + (r0 + 8) * 272 + col * 2) =
                    __floats2half2_rn(acc[mi][nb][2], acc[mi][nb][3]);
            }
        }
        __syncthreads();

        // epilogue: 8 lanes per (edge, half) task; vj/alpha written to CSR slot
        {
            int group = l >> 3, sub = l & 7;
#pragma unroll
            for (int it = 0; it < 4; it++) {
                int T = w * 16 + it * 4 + group;
                int el = T >> 1, hf = T & 1;
                int s = sSrc[el];
                int slot = sSlot[el];

                float f = (sRlt[el] - TH0) * TSCALE;
                int i0 = (int)f;
                i0 = max(0, min(i0, TABN - 2));
                float fr = f - (float)i0;

                int cb = hf * 64 + sub * 8;

                uint4 cu  = *(const uint4*)(sm + el * 272 + cb * 2);
                uint4 qu  = *(const uint4*)(g_qh + (size_t)sDst[el] * 128 + cb);
                uint4 ku  = *(const uint4*)(g_kh + (size_t)s * 128 + cb);
                uint4 vu  = *(const uint4*)(g_vh + (size_t)s * 128 + cb);
                uint4 g0u = *(const uint4*)(g_tab + (size_t)i0 * 128 + cb);
                uint4 g1u = *(const uint4*)(g_tab + (size_t)(i0 + 1) * 128 + cb);

                __half2* q2  = (__half2*)&qu;
                __half2* k2  = (__half2*)&ku;
                __half2* v2  = (__half2*)&vu;
                __half2* c2  = (__half2*)&cu;
                __half2* g02 = (__half2*)&g0u;
                __half2* g12 = (__half2*)&g1u;

                float dot = 0.0f;
                __half2 o2[4];
#pragma unroll
                for (int j = 0; j < 4; j++) {
                    float2 cf = __half22float2(c2[j]);
                    float2 ga = __half22float2(g02[j]);
                    float2 gb = __half22float2(g12[j]);
                    float ea = cf.x + ga.x + fr * (gb.x - ga.x);
                    float eb = cf.y + ga.y + fr * (gb.y - ga.y);
                    float2 qf = __half22float2(q2[j]);
                    float2 kf = __half22float2(k2[j]);
                    float2 vf = __half22float2(v2[j]);
                    dot = fmaf(qf.x, kf.x + ea, dot);
                    dot = fmaf(qf.y, kf.y + eb, dot);
                    o2[j] = __floats2half2_rn(vf.x + ea, vf.y + eb);
                }
                *(uint4*)(g_vj + (size_t)slot * 128 + cb) = *(uint4*)o2;

                dot += __shfl_xor_sync(0xffffffffu, dot, 1);
                dot += __shfl_xor_sync(0xffffffffu, dot, 2);
                dot += __shfl_xor_sync(0xffffffffu, dot, 4);
                if (sub == 0) g_alpha[slot * 2 + hf] = dot * 0.125f;
            }
        }
    }
}

// ---------------- CSR softmax + aggregation: pure streaming ----------------
__global__ void __launch_bounds__(256) k_aggcsr(float* __restrict__ out)
{
    int tid = blockIdx.x * blockDim.x + threadIdx.x;
    int g = tid >> 4, sub = tid & 15;
    if (g >= Nn) return;
    int beg = g_rowstart[g];
    int end = beg + g_cnt[g];
    if (end <= beg) return;

    // pass 1: per-head max (sequential)
    float m0 = -INFINITY, m1 = -INFINITY;
    for (int p = beg + sub; p < end; p += 16) {
        float2 al = *(const float2*)&g_alpha[p * 2];
        m0 = fmaxf(m0, al.x);
        m1 = fmaxf(m1, al.y);
    }
#pragma unroll
    for (int s = 1; s < 16; s <<= 1) {
        m0 = fmaxf(m0, __shfl_xor_sync(0xffffffffu, m0, s, 16));
        m1 = fmaxf(m1, __shfl_xor_sync(0xffffffffu, m1, s, 16));
    }

    // pass 2: exp + sum (first 4 chunks cached in regs)
    float ex0[4], ex1[4];
    float s0 = 0.0f, s1 = 0.0f;
    int nch = min((end - beg + 15) >> 4, 4);
#pragma unroll
    for (int c = 0; c < 4; c++) { ex0[c] = 0.0f; ex1[c] = 0.0f; }
    for (int c = 0; c < nch; c++) {
        int p = beg + c * 16 + sub;
        float a0 = 0.0f, a1 = 0.0f;
        if (p < end) {
            float2 al = *(const float2*)&g_alpha[p * 2];
            a0 = expf(al.x - m0);
            a1 = expf(al.y - m1);
        }
        ex0[c] = a0; ex1[c] = a1;
        s0 += a0; s1 += a1;
    }
    for (int p = beg + 64 + sub; p < end; p += 16) {
        float2 al = *(const float2*)&g_alpha[p * 2];
        s0 += expf(al.x - m0);
        s1 += expf(al.y - m1);
    }
#pragma unroll
    for (int s = 1; s < 16; s <<= 1) {
        s0 += __shfl_xor_sync(0xffffffffu, s0, s, 16);
        s1 += __shfl_xor_sync(0xffffffffu, s1, s, 16);
    }
    float inv = (sub < 8) ? (1.0f / s0) : (1.0f / s1);

    // pass 3: weighted vj accumulation (sequential rows)
    float acc[8];
#pragma unroll
    for (int j = 0; j < 8; j++) acc[j] = 0.0f;

    for (int c = 0; c < nch; c++) {
#pragma unroll
        for (int j = 0; j < 16; j++) {
            int p = beg + c * 16 + j;
            float A = __shfl_sync(0xffffffffu, ex0[c], j, 16);
            float B = __shfl_sync(0xffffffffu, ex1[c], j, 16);
            if (p >= end) break;
            float wv = ((sub < 8) ? A : B) * inv;
            uint4 vju = *(const uint4*)(g_vj + (size_t)p * 128 + sub * 8);
            __half2* v2 = (__half2*)&vju;
#pragma unroll
            for (int q = 0; q < 4; q++) {
                float2 vf = __half22float2(v2[q]);
                acc[q * 2]     = fmaf(wv, vf.x, acc[q * 2]);
                acc[q * 2 + 1] = fmaf(wv, vf.y, acc[q * 2 + 1]);
            }
        }
    }
    for (int p = beg + 64; p < end; p++) {
        float2 al = *(const float2*)&g_alpha[p * 2];
        float wv = ((sub < 8) ? expf(al.x - m0) : expf(al.y - m1)) * inv;
        uint4 vju = *(const uint4*)(g_vj + (size_t)p * 128 + sub * 8);
        __half2* v2 = (__half2*)&vju;
#pragma unroll
        for (int q = 0; q < 4; q++) {
            float2 vf = __half22float2(v2[q]);
            acc[q * 2]     = fmaf(wv, vf.x, acc[q * 2]);
            acc[q * 2 + 1] = fmaf(wv, vf.y, acc[q * 2 + 1]);
        }
    }

    float4* op = (float4*)&out[(size_t)g * 128 + sub * 8];
    float4 o0 = op[0], o1 = op[1];
    o0.x += acc[0]; o0.y += acc[1]; o0.z += acc[2]; o0.w += acc[3];
    o1.x += acc[4]; o1.y += acc[5]; o1.z += acc[6]; o1.w += acc[7];
    op[0] = o0; op[1] = o1;
}

// ---------------- launch ----------------
extern "C" void kernel_launch(void* const* d_in, const int* in_sizes, int n_in,
                              void* d_out, int out_size)
{
    const float* x           = (const float*)d_in[0];
    const float* last_update = (const float*)d_in[1];
    const int*   ei          = (const int*)  d_in[2];
    const float* t           = (const float*)d_in[3];
    const float* msg         = (const float*)d_in[4];
    const float* Wt          = (const float*)d_in[5];
    const float* bt          = (const float*)d_in[6];
    const float* Wq          = (const float*)d_in[7];
    const float* bq          = (const float*)d_in[8];
    const float* Wk          = (const float*)d_in[9];
    const float* bk          = (const float*)d_in[10];
    const float* Wv          = (const float*)d_in[11];
    const float* bv          = (const float*)d_in[12];
    const float* We          = (const float*)d_in[13];
    const float* Wskip       = (const float*)d_in[14];
    const float* bskip       = (const float*)d_in[15];
    float* out = (float*)d_out;

    cudaFuncSetAttribute(k_table,    cudaFuncAttributeMaxDynamicSharedMemorySize, TB_SMEM);
    cudaFuncSetAttribute(k_node_mma, cudaFuncAttributeMaxDynamicSharedMemorySize, NODE_SMEM);
    cudaFuncSetAttribute(k_edge_mma, cudaFuncAttributeMaxDynamicSharedMemorySize, EDGE_SMEM);

    const int NB1 = (Nn + 255) / 256;

    k_prep<<<(Nn * Dd + 255) / 256, 256>>>(x, We, Wq, Wk, Wv, Wskip);

    k_hist<<<(Ee + 255) / 256, 256>>>(ei);
    k_scan1<<<NB1, 256>>>();
    k_scan2<<<1, 256>>>(NB1);
    k_final<<<NB1, 256>>>();
    k_scatter<<<(Ee + 255) / 256, 256>>>(ei);

    k_table<<<296, 256, TB_SMEM>>>(Wt, bt);

    dim3 gn(74, 4);
    k_node_mma<<<gn, 256, NODE_SMEM>>>(bq, bk, bv, bskip, out);

    k_edge_mma<<<296, 512, EDGE_SMEM>>>(ei, last_update, t, msg);

    k_aggcsr<<<(Nn * 16 + 255) / 256, 256>>>(out);
}